// round 7
// baseline (speedup 1.0000x reference)
#include <cuda_runtime.h>
#include <cuda_bf16.h>
#include <cstdint>
#include <math.h>

#define S_        8192
#define HID_      1280
#define H_        16
#define D_        80
#define C_        8
#define L_        1024
#define THREE_HID 3840

// ---------------------------------------------------------------------------
// Scratch (allocation-free rule: __device__ globals)
// ---------------------------------------------------------------------------
__device__ float g_qkv[(size_t)S_ * THREE_HID];
__device__ __nv_bfloat16 g_xhi[(size_t)S_ * HID_];
__device__ __nv_bfloat16 g_xlo[(size_t)S_ * HID_];
__device__ __nv_bfloat16 g_wqt_hi[(size_t)THREE_HID * HID_];  // Wqkv^T [N][K]
__device__ __nv_bfloat16 g_wqt_lo[(size_t)THREE_HID * HID_];
__device__ __nv_bfloat16 g_wpt_hi[(size_t)HID_ * HID_];       // Wproj^T [N][K]
__device__ __nv_bfloat16 g_wpt_lo[(size_t)HID_ * HID_];
__device__ __nv_bfloat16 g_ahi[(size_t)S_ * HID_];            // attn out hi/lo
__device__ __nv_bfloat16 g_alo[(size_t)S_ * HID_];
__device__ __nv_bfloat16 g_qhi[(size_t)H_ * S_ * D_];
__device__ __nv_bfloat16 g_qlo[(size_t)H_ * S_ * D_];
__device__ __nv_bfloat16 g_khi[(size_t)H_ * S_ * D_];
__device__ __nv_bfloat16 g_klo[(size_t)H_ * S_ * D_];
__device__ __nv_bfloat16 g_vhi[(size_t)H_ * S_ * D_];
__device__ __nv_bfloat16 g_vlo[(size_t)H_ * S_ * D_];

__device__ __forceinline__ uint32_t smem_u32(const void* p) {
    uint32_t a;
    asm("{ .reg .u64 t; cvta.to.shared.u64 t, %1; cvt.u32.u64 %0, t; }"
        : "=r"(a) : "l"(p));
    return a;
}
__device__ __forceinline__ uint32_t pk2(float lo, float hi) {
    uint32_t r;
    asm("cvt.rn.bf16x2.f32 %0, %1, %2;" : "=r"(r) : "f"(hi), "f"(lo));
    return r;
}
__device__ __forceinline__ float lo_of(uint32_t p) { return __uint_as_float(p << 16); }
__device__ __forceinline__ float hi_of(uint32_t p) { return __uint_as_float(p & 0xffff0000u); }

#define MMA4(cc, aa, b0, b1)                                                    \
    asm volatile("mma.sync.aligned.m16n8k16.row.col.f32.bf16.bf16.f32 "         \
                 "{%0,%1,%2,%3},{%4,%5,%6,%7},{%8,%9},{%0,%1,%2,%3};"           \
                 : "+f"((cc)[0]), "+f"((cc)[1]), "+f"((cc)[2]), "+f"((cc)[3])   \
                 : "r"((aa)[0]), "r"((aa)[1]), "r"((aa)[2]), "r"((aa)[3]),      \
                   "r"(b0), "r"(b1))
#define LDSM4(r, addr)                                                          \
    asm volatile("ldmatrix.sync.aligned.m8n8.x4.shared.b16 {%0,%1,%2,%3}, [%4];"\
                 : "=r"((r)[0]), "=r"((r)[1]), "=r"((r)[2]), "=r"((r)[3])       \
                 : "r"(addr))
#define LDSM4T(r, addr)                                                         \
    asm volatile("ldmatrix.sync.aligned.m8n8.x4.trans.shared.b16 {%0,%1,%2,%3}, [%4];" \
                 : "=r"((r)[0]), "=r"((r)[1]), "=r"((r)[2]), "=r"((r)[3])       \
                 : "r"(addr))
#define CPA16(dst, src)                                                         \
    asm volatile("cp.async.cg.shared.global [%0], [%1], 16;" :: "r"(dst), "l"(src))

// ---------------------------------------------------------------------------
// bf16-split conversion kernels
// ---------------------------------------------------------------------------
__global__ void split_rows(const float* __restrict__ in,
                           __nv_bfloat16* __restrict__ hi,
                           __nv_bfloat16* __restrict__ lo, int n)
{
    int i = blockIdx.x * blockDim.x + threadIdx.x;
    if (i >= n) return;
    float v = in[i];
    __nv_bfloat16 h = __float2bfloat16(v);
    hi[i] = h;
    lo[i] = __float2bfloat16(v - __bfloat162float(h));
}

__global__ void split_t(const float* __restrict__ W,
                        __nv_bfloat16* __restrict__ hi,
                        __nv_bfloat16* __restrict__ lo, int K, int N)
{
    __shared__ float t[32][33];
    int n0 = blockIdx.x * 32, k0 = blockIdx.y * 32;
    int tx = threadIdx.x, ty = threadIdx.y;   // (32, 8)
#pragma unroll
    for (int i = 0; i < 32; i += 8)
        t[ty + i][tx] = W[(size_t)(k0 + ty + i) * N + n0 + tx];
    __syncthreads();
#pragma unroll
    for (int i = 0; i < 32; i += 8) {
        float v = t[tx][ty + i];
        __nv_bfloat16 h = __float2bfloat16(v);
        size_t o = (size_t)(n0 + ty + i) * K + k0 + tx;
        hi[o] = h;
        lo[o] = __float2bfloat16(v - __bfloat162float(h));
    }
}

// ---------------------------------------------------------------------------
// bf16-split GEMM via mma.sync: C = A @ B^T + bias.
// 128(M) x 256(N) CTA tile, BK=32, 512 threads (16 warps, warp tile 32x64),
// 3-stage cp.async pipeline, 3-term split (Ah*Bh + Ah*Bl + Al*Bh).
// ---------------------------------------------------------------------------
#define AST 40
#define A_BYTES (128 * AST * 2)            // 10240
#define B_BYTES (256 * AST * 2)            // 20480
#define STAGE_BYTES (2 * A_BYTES + 2 * B_BYTES)   // 61440
#define GEMM_SMEM_BYTES (3 * STAGE_BYTES)         // 184320

__global__ __launch_bounds__(512, 1) void mma_gemm_bias(
    const __nv_bfloat16* __restrict__ Ahi, const __nv_bfloat16* __restrict__ Alo,
    const __nv_bfloat16* __restrict__ Bhi, const __nv_bfloat16* __restrict__ Blo,
    const float* __restrict__ bias, float* __restrict__ Cm,
    int M, int N, int K)
{
    extern __shared__ __nv_bfloat16 smb[];
    const uint32_t sb = smem_u32(smb);

    const int tid  = threadIdx.x;
    const int lane = tid & 31, warp = tid >> 5;   // warp 0..15
    const int warpM = warp & 3;                   // rows warpM*32
    const int warpN = warp >> 2;                  // cols warpN*64
    const int quad = lane >> 3, l8 = lane & 7;
    const int tileN = blockIdx.x, tileM = blockIdx.y;

    const __nv_bfloat16* gAh = Ahi + (size_t)(tileM * 128) * K;
    const __nv_bfloat16* gAl = Alo + (size_t)(tileM * 128) * K;
    const __nv_bfloat16* gBh = Bhi + (size_t)(tileN * 256) * K;
    const __nv_bfloat16* gBl = Blo + (size_t)(tileN * 256) * K;

    float c[2][8][4];
#pragma unroll
    for (int mi = 0; mi < 2; mi++)
#pragma unroll
        for (int nt = 0; nt < 8; nt++)
#pragma unroll
            for (int r = 0; r < 4; r++) c[mi][nt][r] = 0.f;

    const int nch = K >> 5;

    auto issue = [&](int ch, int st) {
        const int k0 = ch * 32;
        const uint32_t base = sb + (uint32_t)(st * STAGE_BYTES);
        {   // A: 128 rows x 4 segs = 512 slots -> 1 per thread
            int row = tid >> 2, seg = tid & 3;
            uint32_t so = (uint32_t)((row * AST + seg * 8) * 2);
            size_t go = (size_t)row * K + k0 + seg * 8;
            CPA16(base + so,           gAh + go);
            CPA16(base + A_BYTES + so, gAl + go);
        }
#pragma unroll
        for (int p = 0; p < 2; p++) {   // B: 256 rows x 4 segs = 1024 slots
            int idx = tid + p * 512;
            int row = idx >> 2, seg = idx & 3;
            uint32_t so = (uint32_t)((row * AST + seg * 8) * 2);
            size_t go = (size_t)row * K + k0 + seg * 8;
            CPA16(base + 2 * A_BYTES + so,           gBh + go);
            CPA16(base + 2 * A_BYTES + B_BYTES + so, gBl + go);
        }
        asm volatile("cp.async.commit_group;" ::: "memory");
    };

    issue(0, 0);
    issue(1, 1);

    int st = 0;
    for (int ch = 0; ch < nch; ch++) {
        if (ch + 2 < nch) {
            issue(ch + 2, (st + 2) % 3);
            asm volatile("cp.async.wait_group 2;" ::: "memory");
        } else if (ch + 1 < nch) {
            asm volatile("cp.async.wait_group 1;" ::: "memory");
        } else {
            asm volatile("cp.async.wait_group 0;" ::: "memory");
        }
        __syncthreads();

        const uint32_t base = sb + (uint32_t)(st * STAGE_BYTES);
        const uint32_t aHb = base;
        const uint32_t aLb = base + A_BYTES;
        const uint32_t bHb = base + 2 * A_BYTES;
        const uint32_t bLb = base + 2 * A_BYTES + B_BYTES;

#pragma unroll
        for (int s = 0; s < 2; s++) {
            uint32_t ah[2][4], al[2][4], bh[4][4], bl[4][4];
#pragma unroll
            for (int mi = 0; mi < 2; mi++) {
                int row = warpM * 32 + mi * 16 + (quad & 1) * 8 + l8;
                int ke  = s * 16 + (quad >> 1) * 8;
                LDSM4(ah[mi], aHb + (uint32_t)((row * AST + ke) * 2));
                LDSM4(al[mi], aLb + (uint32_t)((row * AST + ke) * 2));
            }
#pragma unroll
            for (int nj = 0; nj < 4; nj++) {
                int nrow = warpN * 64 + nj * 16 + (quad >> 1) * 8 + l8;
                int ke   = s * 16 + (quad & 1) * 8;
                LDSM4(bh[nj], bHb + (uint32_t)((nrow * AST + ke) * 2));
                LDSM4(bl[nj], bLb + (uint32_t)((nrow * AST + ke) * 2));
            }
#pragma unroll
            for (int mi = 0; mi < 2; mi++) {
#pragma unroll
                for (int nt = 0; nt < 8; nt++) {
                    int nj = nt >> 1, hh = (nt & 1) * 2;
                    MMA4(c[mi][nt], ah[mi], bh[nj][hh], bh[nj][hh + 1]);
                    MMA4(c[mi][nt], ah[mi], bl[nj][hh], bl[nj][hh + 1]);
                    MMA4(c[mi][nt], al[mi], bh[nj][hh], bh[nj][hh + 1]);
                }
            }
        }
        __syncthreads();
        st = (st + 1) % 3;
    }

    const int m0 = tileM * 128 + warpM * 32;
    const int n0 = tileN * 256 + warpN * 64;
    const int rq = lane >> 2, cq = (lane & 3) * 2;
#pragma unroll
    for (int mi = 0; mi < 2; mi++) {
#pragma unroll
        for (int nt = 0; nt < 8; nt++) {
            int col = n0 + nt * 8 + cq;
            float2 b2 = *(const float2*)(bias + col);
            int r0 = m0 + mi * 16 + rq;
            float2 o0, o1;
            o0.x = c[mi][nt][0] + b2.x; o0.y = c[mi][nt][1] + b2.y;
            o1.x = c[mi][nt][2] + b2.x; o1.y = c[mi][nt][3] + b2.y;
            *(float2*)(Cm + (size_t)r0 * N + col)       = o0;
            *(float2*)(Cm + (size_t)(r0 + 8) * N + col) = o1;
        }
    }
}

// ---------------------------------------------------------------------------
// RoPE + split: qkv[S,3*HID] -> bf16 hi/lo Q (pre-scaled), K, V in [H][S][D]
// ---------------------------------------------------------------------------
__global__ void rope_split(const float* __restrict__ cosp,
                           const float* __restrict__ sinp)
{
    int idx = blockIdx.x * blockDim.x + threadIdx.x;
    if (idx >= S_ * HID_) return;
    int s   = idx / HID_;
    int col = idx - s * HID_;
    int h   = col / D_;
    int d   = col - h * D_;

    const float* base = g_qkv + (size_t)s * THREE_HID;
    float qv = base[col];
    float kv = base[HID_ + col];
    float vv = base[2 * HID_ + col];

    float cc = cosp[s * D_ + d];
    float sn = sinp[s * D_ + d];

    int off = (d < 40) ? (col + 40) : (col - 40);
    float sgn = (d < 40) ? -1.f : 1.f;
    float qrot = sgn * base[off];
    float krot = sgn * base[HID_ + off];

    const float inv_scale = rsqrtf((float)D_);
    float qf = (qv * cc + qrot * sn) * inv_scale;
    float kf = kv * cc + krot * sn;

    size_t o = (size_t)h * S_ * D_ + (size_t)s * D_ + d;
    __nv_bfloat16 qh = __float2bfloat16(qf);
    __nv_bfloat16 kh = __float2bfloat16(kf);
    __nv_bfloat16 vh = __float2bfloat16(vv);
    g_qhi[o] = qh; g_qlo[o] = __float2bfloat16(qf - __bfloat162float(qh));
    g_khi[o] = kh; g_klo[o] = __float2bfloat16(kf - __bfloat162float(kh));
    g_vhi[o] = vh; g_vlo[o] = __float2bfloat16(vv - __bfloat162float(vh));
}

// ---------------------------------------------------------------------------
// HMMA flash attention. 128q rows/CTA, 64k tiles, 8 warps (16 rows each).
// ---------------------------------------------------------------------------
#define ATT_STRIDE 88
#define Q_BYTES (128 * ATT_STRIDE * 2)
#define T_BYTES (64 * ATT_STRIDE * 2)
#define OFF_QH 0
#define OFF_QL Q_BYTES
#define OFF_KH (2 * Q_BYTES)
#define OFF_KL (2 * Q_BYTES + 2 * T_BYTES)
#define OFF_VH (2 * Q_BYTES + 4 * T_BYTES)
#define OFF_VL (2 * Q_BYTES + 6 * T_BYTES)
#define ATTN_SMEM_BYTES (2 * Q_BYTES + 8 * T_BYTES)   // 135168

__global__ __launch_bounds__(256) void attn_mma()
{
    extern __shared__ char smc[];
    const uint32_t sb = smem_u32(smc);

    const int bx = blockIdx.x;
    const int qt = bx & 7;
    const int h  = (bx >> 3) & 15;
    const int c  = bx >> 7;

    const int tid = threadIdx.x;
    const int lane = tid & 31, w = tid >> 5;
    const int quad = lane >> 3, l8 = lane & 7;

    const size_t hq = (size_t)h * S_ * D_ + (size_t)(c * L_ + qt * 128) * D_;
    const size_t hk = (size_t)h * S_ * D_ + (size_t)(c * L_) * D_;

    for (int i = tid; i < 1280; i += 256) {
        int row = i / 10, seg = i - row * 10;
        uint32_t off = (uint32_t)(row * ATT_STRIDE + seg * 8) * 2;
        size_t g = hq + (size_t)row * 80 + seg * 8;
        CPA16(sb + OFF_QH + off, g_qhi + g);
        CPA16(sb + OFF_QL + off, g_qlo + g);
    }
    for (int i = tid; i < 640; i += 256) {
        int row = i / 10, seg = i - row * 10;
        uint32_t off = (uint32_t)(row * ATT_STRIDE + seg * 8) * 2;
        size_t g = hk + (size_t)row * 80 + seg * 8;
        CPA16(sb + OFF_KH + off, g_khi + g);
        CPA16(sb + OFF_KL + off, g_klo + g);
        CPA16(sb + OFF_VH + off, g_vhi + g);
        CPA16(sb + OFF_VL + off, g_vlo + g);
    }
    asm volatile("cp.async.commit_group;" ::: "memory");

    float m_a = -1e30f, m_b = -1e30f, l_a = 0.f, l_b = 0.f;
    float out[10][4];
#pragma unroll
    for (int vt = 0; vt < 10; vt++)
#pragma unroll
        for (int r = 0; r < 4; r++) out[vt][r] = 0.f;

    for (int t = 0; t < 16; t++) {
        if (t + 1 < 16) {
            const uint32_t s1 = ((t + 1) & 1) * T_BYTES;
            const size_t tb = hk + (size_t)(t + 1) * 64 * 80;
            for (int i = tid; i < 640; i += 256) {
                int row = i / 10, seg = i - row * 10;
                uint32_t off = (uint32_t)(row * ATT_STRIDE + seg * 8) * 2 + s1;
                size_t g = tb + (size_t)row * 80 + seg * 8;
                CPA16(sb + OFF_KH + off, g_khi + g);
                CPA16(sb + OFF_KL + off, g_klo + g);
                CPA16(sb + OFF_VH + off, g_vhi + g);
                CPA16(sb + OFF_VL + off, g_vlo + g);
            }
            asm volatile("cp.async.commit_group;" ::: "memory");
            asm volatile("cp.async.wait_group 1;" ::: "memory");
        } else {
            asm volatile("cp.async.wait_group 0;" ::: "memory");
        }
        __syncthreads();

        const uint32_t stg = (t & 1) * T_BYTES;
        const uint32_t KHs = sb + OFF_KH + stg;
        const uint32_t KLs = sb + OFF_KL + stg;
        const uint32_t VHs = sb + OFF_VH + stg;
        const uint32_t VLs = sb + OFF_VL + stg;

        float sc[8][4];
#pragma unroll
        for (int nt = 0; nt < 8; nt++)
#pragma unroll
            for (int r = 0; r < 4; r++) sc[nt][r] = 0.f;

        const int arow = w * 16 + (quad & 1) * 8 + l8;
#pragma unroll
        for (int kk = 0; kk < 5; kk++) {
            uint32_t ah[4], al[4];
            uint32_t aoff = (uint32_t)(arow * ATT_STRIDE + kk * 16 + (quad >> 1) * 8) * 2;
            LDSM4(ah, sb + OFF_QH + aoff);
            LDSM4(al, sb + OFF_QL + aoff);
#pragma unroll
            for (int nj = 0; nj < 4; nj++) {
                uint32_t bh[4], bl[4];
                uint32_t boff = (uint32_t)((nj * 16 + (quad >> 1) * 8 + l8) * ATT_STRIDE
                                           + kk * 16 + (quad & 1) * 8) * 2;
                LDSM4(bh, KHs + boff);
                LDSM4(bl, KLs + boff);
                MMA4(sc[2 * nj],     ah, bh[0], bh[1]);
                MMA4(sc[2 * nj],     ah, bl[0], bl[1]);
                MMA4(sc[2 * nj],     al, bh[0], bh[1]);
                MMA4(sc[2 * nj + 1], ah, bh[2], bh[3]);
                MMA4(sc[2 * nj + 1], ah, bl[2], bl[3]);
                MMA4(sc[2 * nj + 1], al, bh[2], bh[3]);
            }
        }

        float mxa = sc[0][0], mxb = sc[0][2];
#pragma unroll
        for (int nt = 0; nt < 8; nt++) {
            mxa = fmaxf(mxa, fmaxf(sc[nt][0], sc[nt][1]));
            mxb = fmaxf(mxb, fmaxf(sc[nt][2], sc[nt][3]));
        }
        mxa = fmaxf(mxa, __shfl_xor_sync(0xffffffffu, mxa, 1));
        mxa = fmaxf(mxa, __shfl_xor_sync(0xffffffffu, mxa, 2));
        mxb = fmaxf(mxb, __shfl_xor_sync(0xffffffffu, mxb, 1));
        mxb = fmaxf(mxb, __shfl_xor_sync(0xffffffffu, mxb, 2));
        float nma = fmaxf(m_a, mxa), nmb = fmaxf(m_b, mxb);
        float ca  = __expf(m_a - nma), cb = __expf(m_b - nmb);
        m_a = nma; m_b = nmb;

        float sa = 0.f, sbv = 0.f;
#pragma unroll
        for (int nt = 0; nt < 8; nt++) {
            sc[nt][0] = __expf(sc[nt][0] - m_a);
            sc[nt][1] = __expf(sc[nt][1] - m_a);
            sc[nt][2] = __expf(sc[nt][2] - m_b);
            sc[nt][3] = __expf(sc[nt][3] - m_b);
            sa  += sc[nt][0] + sc[nt][1];
            sbv += sc[nt][2] + sc[nt][3];
        }
        sa  += __shfl_xor_sync(0xffffffffu, sa, 1);
        sa  += __shfl_xor_sync(0xffffffffu, sa, 2);
        sbv += __shfl_xor_sync(0xffffffffu, sbv, 1);
        sbv += __shfl_xor_sync(0xffffffffu, sbv, 2);
        l_a = l_a * ca + sa;
        l_b = l_b * cb + sbv;

        uint32_t Ph[4][4], Pl[4][4];
#pragma unroll
        for (int kk = 0; kk < 4; kk++) {
#pragma unroll
            for (int half = 0; half < 2; half++) {
                int nt = 2 * kk + half;
                uint32_t h0 = pk2(sc[nt][0], sc[nt][1]);
                uint32_t h1 = pk2(sc[nt][2], sc[nt][3]);
                Ph[kk][2 * half + 0] = h0;
                Ph[kk][2 * half + 1] = h1;
                Pl[kk][2 * half + 0] = pk2(sc[nt][0] - lo_of(h0), sc[nt][1] - hi_of(h0));
                Pl[kk][2 * half + 1] = pk2(sc[nt][2] - lo_of(h1), sc[nt][3] - hi_of(h1));
            }
        }

#pragma unroll
        for (int vt = 0; vt < 10; vt++) {
            out[vt][0] *= ca; out[vt][1] *= ca;
            out[vt][2] *= cb; out[vt][3] *= cb;
        }

#pragma unroll
        for (int kk = 0; kk < 4; kk++) {
#pragma unroll
            for (int vj = 0; vj < 5; vj++) {
                uint32_t vhf[4], vlf[4];
                uint32_t voff = (uint32_t)((kk * 16 + (quad & 1) * 8 + l8) * ATT_STRIDE
                                           + vj * 16 + (quad >> 1) * 8) * 2;
                LDSM4T(vhf, VHs + voff);
                LDSM4T(vlf, VLs + voff);
                MMA4(out[2 * vj],     Ph[kk], vhf[0], vhf[1]);
                MMA4(out[2 * vj],     Ph[kk], vlf[0], vlf[1]);
                MMA4(out[2 * vj],     Pl[kk], vhf[0], vhf[1]);
                MMA4(out[2 * vj + 1], Ph[kk], vhf[2], vhf[3]);
                MMA4(out[2 * vj + 1], Ph[kk], vlf[2], vlf[3]);
                MMA4(out[2 * vj + 1], Pl[kk], vhf[2], vhf[3]);
            }
        }
        __syncthreads();
    }

    float ila = 1.f / l_a, ilb = 1.f / l_b;
    int ra = c * L_ + qt * 128 + w * 16 + (lane >> 2);
    int colb = h * D_ + (lane & 3) * 2;
#pragma unroll
    for (int vt = 0; vt < 10; vt++) {
        int col = colb + vt * 8;
        float v0 = out[vt][0] * ila, v1 = out[vt][1] * ila;
        uint32_t hp = pk2(v0, v1);
        uint32_t lp = pk2(v0 - lo_of(hp), v1 - hi_of(hp));
        *(uint32_t*)(g_ahi + (size_t)ra * HID_ + col) = hp;
        *(uint32_t*)(g_alo + (size_t)ra * HID_ + col) = lp;
        float v2 = out[vt][2] * ilb, v3 = out[vt][3] * ilb;
        hp = pk2(v2, v3);
        lp = pk2(v2 - lo_of(hp), v3 - hi_of(hp));
        *(uint32_t*)(g_ahi + (size_t)(ra + 8) * HID_ + col) = hp;
        *(uint32_t*)(g_alo + (size_t)(ra + 8) * HID_ + col) = lp;
    }
}

// ---------------------------------------------------------------------------
// Launch pipeline
// ---------------------------------------------------------------------------
extern "C" void kernel_launch(void* const* d_in, const int* in_sizes, int n_in,
                              void* d_out, int out_size)
{
    const float* x     = (const float*)d_in[0];
    const float* cosp  = (const float*)d_in[1];
    const float* sinp  = (const float*)d_in[2];
    const float* Wqkv  = (const float*)d_in[3];
    const float* bqkv  = (const float*)d_in[4];
    const float* Wproj = (const float*)d_in[5];
    const float* bproj = (const float*)d_in[6];
    float* out = (float*)d_out;

    float* qkv_p;
    __nv_bfloat16 *xhi, *xlo, *wqh, *wql, *wph, *wpl, *ahi, *alo;
    cudaGetSymbolAddress((void**)&qkv_p, g_qkv);
    cudaGetSymbolAddress((void**)&xhi, g_xhi);
    cudaGetSymbolAddress((void**)&xlo, g_xlo);
    cudaGetSymbolAddress((void**)&wqh, g_wqt_hi);
    cudaGetSymbolAddress((void**)&wql, g_wqt_lo);
    cudaGetSymbolAddress((void**)&wph, g_wpt_hi);
    cudaGetSymbolAddress((void**)&wpl, g_wpt_lo);
    cudaGetSymbolAddress((void**)&ahi, g_ahi);
    cudaGetSymbolAddress((void**)&alo, g_alo);

    static int attr_set = 0;
    if (!attr_set) {
        cudaFuncSetAttribute(attn_mma,
                             cudaFuncAttributeMaxDynamicSharedMemorySize,
                             ATTN_SMEM_BYTES);
        cudaFuncSetAttribute(mma_gemm_bias,
                             cudaFuncAttributeMaxDynamicSharedMemorySize,
                             GEMM_SMEM_BYTES);
        attr_set = 1;
    }

    split_rows<<<(S_ * HID_ + 255) / 256, 256>>>(x, xhi, xlo, S_ * HID_);
    split_t<<<dim3(THREE_HID / 32, HID_ / 32), dim3(32, 8)>>>(Wqkv, wqh, wql, HID_, THREE_HID);
    split_t<<<dim3(HID_ / 32, HID_ / 32), dim3(32, 8)>>>(Wproj, wph, wpl, HID_, HID_);

    mma_gemm_bias<<<dim3(THREE_HID / 256, S_ / 128), 512, GEMM_SMEM_BYTES>>>(
        xhi, xlo, wqh, wql, bqkv, qkv_p, S_, THREE_HID, HID_);

    rope_split<<<(S_ * HID_ + 255) / 256, 256>>>(cosp, sinp);

    attn_mma<<<C_ * H_ * (L_ / 128), 256, ATTN_SMEM_BYTES>>>();

    mma_gemm_bias<<<dim3(HID_ / 256, S_ / 128), 512, GEMM_SMEM_BYTES>>>(
        ahi, alo, wph, wpl, bproj, out, S_, HID_, HID_);
}

// round 8
// speedup vs baseline: 1.7461x; 1.7461x over previous
#include <cuda_runtime.h>
#include <cuda_bf16.h>
#include <cstdint>
#include <math.h>

#define S_        8192
#define HID_      1280
#define H_        16
#define D_        80
#define C_        8
#define L_        1024
#define THREE_HID 3840

// ---------------------------------------------------------------------------
// Scratch (allocation-free rule: __device__ globals)
// ---------------------------------------------------------------------------
__device__ float g_qkv[(size_t)S_ * THREE_HID];
__device__ __nv_bfloat16 g_xhi[(size_t)S_ * HID_];
__device__ __nv_bfloat16 g_xlo[(size_t)S_ * HID_];
__device__ __nv_bfloat16 g_wqt_hi[(size_t)THREE_HID * HID_];  // Wqkv^T [N][K]
__device__ __nv_bfloat16 g_wqt_lo[(size_t)THREE_HID * HID_];
__device__ __nv_bfloat16 g_wpt_hi[(size_t)HID_ * HID_];       // Wproj^T [N][K]
__device__ __nv_bfloat16 g_wpt_lo[(size_t)HID_ * HID_];
__device__ __nv_bfloat16 g_ahi[(size_t)S_ * HID_];            // attn out hi/lo
__device__ __nv_bfloat16 g_alo[(size_t)S_ * HID_];
__device__ __nv_bfloat16 g_qhi[(size_t)H_ * S_ * D_];
__device__ __nv_bfloat16 g_qlo[(size_t)H_ * S_ * D_];
__device__ __nv_bfloat16 g_khi[(size_t)H_ * S_ * D_];
__device__ __nv_bfloat16 g_klo[(size_t)H_ * S_ * D_];
__device__ __nv_bfloat16 g_vhi[(size_t)H_ * S_ * D_];
__device__ __nv_bfloat16 g_vlo[(size_t)H_ * S_ * D_];

__device__ __forceinline__ uint32_t smem_u32(const void* p) {
    uint32_t a;
    asm("{ .reg .u64 t; cvta.to.shared.u64 t, %1; cvt.u32.u64 %0, t; }"
        : "=r"(a) : "l"(p));
    return a;
}
__device__ __forceinline__ uint32_t pk2(float lo, float hi) {
    uint32_t r;
    asm("cvt.rn.bf16x2.f32 %0, %1, %2;" : "=r"(r) : "f"(hi), "f"(lo));
    return r;
}
__device__ __forceinline__ float lo_of(uint32_t p) { return __uint_as_float(p << 16); }
__device__ __forceinline__ float hi_of(uint32_t p) { return __uint_as_float(p & 0xffff0000u); }

#define MMA4(cc, aa, b0, b1)                                                    \
    asm volatile("mma.sync.aligned.m16n8k16.row.col.f32.bf16.bf16.f32 "         \
                 "{%0,%1,%2,%3},{%4,%5,%6,%7},{%8,%9},{%0,%1,%2,%3};"           \
                 : "+f"((cc)[0]), "+f"((cc)[1]), "+f"((cc)[2]), "+f"((cc)[3])   \
                 : "r"((aa)[0]), "r"((aa)[1]), "r"((aa)[2]), "r"((aa)[3]),      \
                   "r"(b0), "r"(b1))
#define LDSM4(r, addr)                                                          \
    asm volatile("ldmatrix.sync.aligned.m8n8.x4.shared.b16 {%0,%1,%2,%3}, [%4];"\
                 : "=r"((r)[0]), "=r"((r)[1]), "=r"((r)[2]), "=r"((r)[3])       \
                 : "r"(addr))
#define LDSM4T(r, addr)                                                         \
    asm volatile("ldmatrix.sync.aligned.m8n8.x4.trans.shared.b16 {%0,%1,%2,%3}, [%4];" \
                 : "=r"((r)[0]), "=r"((r)[1]), "=r"((r)[2]), "=r"((r)[3])       \
                 : "r"(addr))
#define CPA16(dst, src)                                                         \
    asm volatile("cp.async.cg.shared.global [%0], [%1], 16;" :: "r"(dst), "l"(src))

// ---------------------------------------------------------------------------
// bf16-split conversion kernels
// ---------------------------------------------------------------------------
__global__ void split_rows(const float* __restrict__ in,
                           __nv_bfloat16* __restrict__ hi,
                           __nv_bfloat16* __restrict__ lo, int n)
{
    int i = blockIdx.x * blockDim.x + threadIdx.x;
    if (i >= n) return;
    float v = in[i];
    __nv_bfloat16 h = __float2bfloat16(v);
    hi[i] = h;
    lo[i] = __float2bfloat16(v - __bfloat162float(h));
}

__global__ void split_t(const float* __restrict__ W,
                        __nv_bfloat16* __restrict__ hi,
                        __nv_bfloat16* __restrict__ lo, int K, int N)
{
    __shared__ float t[32][33];
    int n0 = blockIdx.x * 32, k0 = blockIdx.y * 32;
    int tx = threadIdx.x, ty = threadIdx.y;   // (32, 8)
#pragma unroll
    for (int i = 0; i < 32; i += 8)
        t[ty + i][tx] = W[(size_t)(k0 + ty + i) * N + n0 + tx];
    __syncthreads();
#pragma unroll
    for (int i = 0; i < 32; i += 8) {
        float v = t[tx][ty + i];
        __nv_bfloat16 h = __float2bfloat16(v);
        size_t o = (size_t)(n0 + ty + i) * K + k0 + tx;
        hi[o] = h;
        lo[o] = __float2bfloat16(v - __bfloat162float(h));
    }
}

// ---------------------------------------------------------------------------
// bf16-split GEMM via mma.sync: C = A @ B^T + bias.  (R6 proven config)
// 128x128 CTA tile, BK=32, 256 threads (8 warps, warp tile 32x64),
// double-buffered cp.async, 2 CTAs/SM.  3-term split: Ah*Bh + Ah*Bl + Al*Bh.
// ---------------------------------------------------------------------------
#define AST 40
#define MAT_ELEMS (128 * AST)
#define GEMM_SMEM_BYTES (2 * 4 * MAT_ELEMS * 2)   // 81920

__global__ __launch_bounds__(256, 2) void mma_gemm_bias(
    const __nv_bfloat16* __restrict__ Ahi, const __nv_bfloat16* __restrict__ Alo,
    const __nv_bfloat16* __restrict__ Bhi, const __nv_bfloat16* __restrict__ Blo,
    const float* __restrict__ bias, float* __restrict__ Cm,
    int M, int N, int K)
{
    extern __shared__ __nv_bfloat16 smb[];
    const uint32_t sb = smem_u32(smb);

    const int tid  = threadIdx.x;
    const int lane = tid & 31, warp = tid >> 5;
    const int warpM = warp & 3;
    const int warpN = warp >> 2;
    const int quad = lane >> 3, l8 = lane & 7;
    const int tileN = blockIdx.x, tileM = blockIdx.y;

    const __nv_bfloat16* gAh = Ahi + (size_t)(tileM * 128) * K;
    const __nv_bfloat16* gAl = Alo + (size_t)(tileM * 128) * K;
    const __nv_bfloat16* gBh = Bhi + (size_t)(tileN * 128) * K;
    const __nv_bfloat16* gBl = Blo + (size_t)(tileN * 128) * K;

    float c[2][8][4];
#pragma unroll
    for (int mi = 0; mi < 2; mi++)
#pragma unroll
        for (int nt = 0; nt < 8; nt++)
#pragma unroll
            for (int r = 0; r < 4; r++) c[mi][nt][r] = 0.f;

    const int nch = K >> 5;

    auto issue = [&](int ch, int buf) {
        const int k0 = ch * 32;
#pragma unroll
        for (int p = 0; p < 2; p++) {
            int idx = tid + p * 256;
            int row = idx >> 2, seg = idx & 3;
            uint32_t so = (uint32_t)((row * AST + seg * 8) * 2);
            size_t go = (size_t)row * K + k0 + seg * 8;
            uint32_t s0 = sb + (uint32_t)(buf * 4 * MAT_ELEMS * 2) + so;
            CPA16(s0,                     gAh + go);
            CPA16(s0 + 1 * MAT_ELEMS * 2, gAl + go);
            CPA16(s0 + 2 * MAT_ELEMS * 2, gBh + go);
            CPA16(s0 + 3 * MAT_ELEMS * 2, gBl + go);
        }
        asm volatile("cp.async.commit_group;" ::: "memory");
    };

    issue(0, 0);

    for (int ch = 0; ch < nch; ch++) {
        if (ch + 1 < nch) {
            issue(ch + 1, (ch + 1) & 1);
            asm volatile("cp.async.wait_group 1;" ::: "memory");
        } else {
            asm volatile("cp.async.wait_group 0;" ::: "memory");
        }
        __syncthreads();

        const uint32_t base = sb + (uint32_t)((ch & 1) * 4 * MAT_ELEMS * 2);
        const uint32_t aHb = base;
        const uint32_t aLb = base + 1 * MAT_ELEMS * 2;
        const uint32_t bHb = base + 2 * MAT_ELEMS * 2;
        const uint32_t bLb = base + 3 * MAT_ELEMS * 2;

#pragma unroll
        for (int s = 0; s < 2; s++) {
            uint32_t ah[2][4], al[2][4], bh[4][4], bl[4][4];
#pragma unroll
            for (int mi = 0; mi < 2; mi++) {
                int row = warpM * 32 + mi * 16 + (quad & 1) * 8 + l8;
                int ke  = s * 16 + (quad >> 1) * 8;
                LDSM4(ah[mi], aHb + (uint32_t)((row * AST + ke) * 2));
                LDSM4(al[mi], aLb + (uint32_t)((row * AST + ke) * 2));
            }
#pragma unroll
            for (int nj = 0; nj < 4; nj++) {
                int nrow = warpN * 64 + nj * 16 + (quad >> 1) * 8 + l8;
                int ke   = s * 16 + (quad & 1) * 8;
                LDSM4(bh[nj], bHb + (uint32_t)((nrow * AST + ke) * 2));
                LDSM4(bl[nj], bLb + (uint32_t)((nrow * AST + ke) * 2));
            }
#pragma unroll
            for (int mi = 0; mi < 2; mi++) {
#pragma unroll
                for (int nt = 0; nt < 8; nt++) {
                    int nj = nt >> 1, hh = (nt & 1) * 2;
                    MMA4(c[mi][nt], ah[mi], bh[nj][hh], bh[nj][hh + 1]);
                    MMA4(c[mi][nt], ah[mi], bl[nj][hh], bl[nj][hh + 1]);
                    MMA4(c[mi][nt], al[mi], bh[nj][hh], bh[nj][hh + 1]);
                }
            }
        }
        __syncthreads();
    }

    const int m0 = tileM * 128 + warpM * 32;
    const int n0 = tileN * 128 + warpN * 64;
    const int rq = lane >> 2, cq = (lane & 3) * 2;
#pragma unroll
    for (int mi = 0; mi < 2; mi++) {
#pragma unroll
        for (int nt = 0; nt < 8; nt++) {
            int col = n0 + nt * 8 + cq;
            float2 b2 = *(const float2*)(bias + col);
            int r0 = m0 + mi * 16 + rq;
            float2 o0, o1;
            o0.x = c[mi][nt][0] + b2.x; o0.y = c[mi][nt][1] + b2.y;
            o1.x = c[mi][nt][2] + b2.x; o1.y = c[mi][nt][3] + b2.y;
            *(float2*)(Cm + (size_t)r0 * N + col)       = o0;
            *(float2*)(Cm + (size_t)(r0 + 8) * N + col) = o1;
        }
    }
}

// ---------------------------------------------------------------------------
// Experimental small-CTA GEMM: 64(M) x 128(N) tile, 128 threads (4 warps,
// warp tile 32x64 — identical warp-level code), 3 CTAs/SM.  Used for proj.
// ---------------------------------------------------------------------------
#define A64_BYTES (64 * AST * 2)           // 5120
#define B128_BYTES (128 * AST * 2)         // 10240
#define STAGE_SM (2 * A64_BYTES + 2 * B128_BYTES)   // 30720
#define GEMM_SM_SMEM_BYTES (2 * STAGE_SM)           // 61440

__global__ __launch_bounds__(128, 3) void mma_gemm_bias_sm(
    const __nv_bfloat16* __restrict__ Ahi, const __nv_bfloat16* __restrict__ Alo,
    const __nv_bfloat16* __restrict__ Bhi, const __nv_bfloat16* __restrict__ Blo,
    const float* __restrict__ bias, float* __restrict__ Cm,
    int M, int N, int K)
{
    extern __shared__ __nv_bfloat16 smb[];
    const uint32_t sb = smem_u32(smb);

    const int tid  = threadIdx.x;
    const int lane = tid & 31, warp = tid >> 5;   // 0..3
    const int warpM = warp & 1;                   // rows warpM*32
    const int warpN = warp >> 1;                  // cols warpN*64
    const int quad = lane >> 3, l8 = lane & 7;
    const int tileN = blockIdx.x, tileM = blockIdx.y;

    const __nv_bfloat16* gAh = Ahi + (size_t)(tileM * 64) * K;
    const __nv_bfloat16* gAl = Alo + (size_t)(tileM * 64) * K;
    const __nv_bfloat16* gBh = Bhi + (size_t)(tileN * 128) * K;
    const __nv_bfloat16* gBl = Blo + (size_t)(tileN * 128) * K;

    float c[2][8][4];
#pragma unroll
    for (int mi = 0; mi < 2; mi++)
#pragma unroll
        for (int nt = 0; nt < 8; nt++)
#pragma unroll
            for (int r = 0; r < 4; r++) c[mi][nt][r] = 0.f;

    const int nch = K >> 5;

    auto issue = [&](int ch, int buf) {
        const int k0 = ch * 32;
        const uint32_t base = sb + (uint32_t)(buf * STAGE_SM);
#pragma unroll
        for (int p = 0; p < 2; p++) {    // A: 64 rows x 4 segs = 256 slots
            int idx = tid + p * 128;
            int row = idx >> 2, seg = idx & 3;
            uint32_t so = (uint32_t)((row * AST + seg * 8) * 2);
            size_t go = (size_t)row * K + k0 + seg * 8;
            CPA16(base + so,             gAh + go);
            CPA16(base + A64_BYTES + so, gAl + go);
        }
#pragma unroll
        for (int p = 0; p < 4; p++) {    // B: 128 rows x 4 segs = 512 slots
            int idx = tid + p * 128;
            int row = idx >> 2, seg = idx & 3;
            uint32_t so = (uint32_t)((row * AST + seg * 8) * 2);
            size_t go = (size_t)row * K + k0 + seg * 8;
            CPA16(base + 2 * A64_BYTES + so,              gBh + go);
            CPA16(base + 2 * A64_BYTES + B128_BYTES + so, gBl + go);
        }
        asm volatile("cp.async.commit_group;" ::: "memory");
    };

    issue(0, 0);

    for (int ch = 0; ch < nch; ch++) {
        if (ch + 1 < nch) {
            issue(ch + 1, (ch + 1) & 1);
            asm volatile("cp.async.wait_group 1;" ::: "memory");
        } else {
            asm volatile("cp.async.wait_group 0;" ::: "memory");
        }
        __syncthreads();

        const uint32_t base = sb + (uint32_t)((ch & 1) * STAGE_SM);
        const uint32_t aHb = base;
        const uint32_t aLb = base + A64_BYTES;
        const uint32_t bHb = base + 2 * A64_BYTES;
        const uint32_t bLb = base + 2 * A64_BYTES + B128_BYTES;

#pragma unroll
        for (int s = 0; s < 2; s++) {
            uint32_t ah[2][4], al[2][4], bh[4][4], bl[4][4];
#pragma unroll
            for (int mi = 0; mi < 2; mi++) {
                int row = warpM * 32 + mi * 16 + (quad & 1) * 8 + l8;
                int ke  = s * 16 + (quad >> 1) * 8;
                LDSM4(ah[mi], aHb + (uint32_t)((row * AST + ke) * 2));
                LDSM4(al[mi], aLb + (uint32_t)((row * AST + ke) * 2));
            }
#pragma unroll
            for (int nj = 0; nj < 4; nj++) {
                int nrow = warpN * 64 + nj * 16 + (quad >> 1) * 8 + l8;
                int ke   = s * 16 + (quad & 1) * 8;
                LDSM4(bh[nj], bHb + (uint32_t)((nrow * AST + ke) * 2));
                LDSM4(bl[nj], bLb + (uint32_t)((nrow * AST + ke) * 2));
            }
#pragma unroll
            for (int mi = 0; mi < 2; mi++) {
#pragma unroll
                for (int nt = 0; nt < 8; nt++) {
                    int nj = nt >> 1, hh = (nt & 1) * 2;
                    MMA4(c[mi][nt], ah[mi], bh[nj][hh], bh[nj][hh + 1]);
                    MMA4(c[mi][nt], ah[mi], bl[nj][hh], bl[nj][hh + 1]);
                    MMA4(c[mi][nt], al[mi], bh[nj][hh], bh[nj][hh + 1]);
                }
            }
        }
        __syncthreads();
    }

    const int m0 = tileM * 64 + warpM * 32;
    const int n0 = tileN * 128 + warpN * 64;
    const int rq = lane >> 2, cq = (lane & 3) * 2;
#pragma unroll
    for (int mi = 0; mi < 2; mi++) {
#pragma unroll
        for (int nt = 0; nt < 8; nt++) {
            int col = n0 + nt * 8 + cq;
            float2 b2 = *(const float2*)(bias + col);
            int r0 = m0 + mi * 16 + rq;
            float2 o0, o1;
            o0.x = c[mi][nt][0] + b2.x; o0.y = c[mi][nt][1] + b2.y;
            o1.x = c[mi][nt][2] + b2.x; o1.y = c[mi][nt][3] + b2.y;
            *(float2*)(Cm + (size_t)r0 * N + col)       = o0;
            *(float2*)(Cm + (size_t)(r0 + 8) * N + col) = o1;
        }
    }
}

// ---------------------------------------------------------------------------
// RoPE + split: qkv[S,3*HID] -> bf16 hi/lo Q (pre-scaled), K, V in [H][S][D]
// ---------------------------------------------------------------------------
__global__ void rope_split(const float* __restrict__ cosp,
                           const float* __restrict__ sinp)
{
    int idx = blockIdx.x * blockDim.x + threadIdx.x;
    if (idx >= S_ * HID_) return;
    int s   = idx / HID_;
    int col = idx - s * HID_;
    int h   = col / D_;
    int d   = col - h * D_;

    const float* base = g_qkv + (size_t)s * THREE_HID;
    float qv = base[col];
    float kv = base[HID_ + col];
    float vv = base[2 * HID_ + col];

    float cc = cosp[s * D_ + d];
    float sn = sinp[s * D_ + d];

    int off = (d < 40) ? (col + 40) : (col - 40);
    float sgn = (d < 40) ? -1.f : 1.f;
    float qrot = sgn * base[off];
    float krot = sgn * base[HID_ + off];

    const float inv_scale = rsqrtf((float)D_);
    float qf = (qv * cc + qrot * sn) * inv_scale;
    float kf = kv * cc + krot * sn;

    size_t o = (size_t)h * S_ * D_ + (size_t)s * D_ + d;
    __nv_bfloat16 qh = __float2bfloat16(qf);
    __nv_bfloat16 kh = __float2bfloat16(kf);
    __nv_bfloat16 vh = __float2bfloat16(vv);
    g_qhi[o] = qh; g_qlo[o] = __float2bfloat16(qf - __bfloat162float(qh));
    g_khi[o] = kh; g_klo[o] = __float2bfloat16(kf - __bfloat162float(kh));
    g_vhi[o] = vh; g_vlo[o] = __float2bfloat16(vv - __bfloat162float(vh));
}

// ---------------------------------------------------------------------------
// HMMA flash attention. 128q rows/CTA, 64k tiles, 8 warps (16 rows each).
// ---------------------------------------------------------------------------
#define ATT_STRIDE 88
#define Q_BYTES (128 * ATT_STRIDE * 2)
#define T_BYTES (64 * ATT_STRIDE * 2)
#define OFF_QH 0
#define OFF_QL Q_BYTES
#define OFF_KH (2 * Q_BYTES)
#define OFF_KL (2 * Q_BYTES + 2 * T_BYTES)
#define OFF_VH (2 * Q_BYTES + 4 * T_BYTES)
#define OFF_VL (2 * Q_BYTES + 6 * T_BYTES)
#define ATTN_SMEM_BYTES (2 * Q_BYTES + 8 * T_BYTES)   // 135168

__global__ __launch_bounds__(256) void attn_mma()
{
    extern __shared__ char smc[];
    const uint32_t sb = smem_u32(smc);

    const int bx = blockIdx.x;
    const int qt = bx & 7;
    const int h  = (bx >> 3) & 15;
    const int c  = bx >> 7;

    const int tid = threadIdx.x;
    const int lane = tid & 31, w = tid >> 5;
    const int quad = lane >> 3, l8 = lane & 7;

    const size_t hq = (size_t)h * S_ * D_ + (size_t)(c * L_ + qt * 128) * D_;
    const size_t hk = (size_t)h * S_ * D_ + (size_t)(c * L_) * D_;

    for (int i = tid; i < 1280; i += 256) {
        int row = i / 10, seg = i - row * 10;
        uint32_t off = (uint32_t)(row * ATT_STRIDE + seg * 8) * 2;
        size_t g = hq + (size_t)row * 80 + seg * 8;
        CPA16(sb + OFF_QH + off, g_qhi + g);
        CPA16(sb + OFF_QL + off, g_qlo + g);
    }
    for (int i = tid; i < 640; i += 256) {
        int row = i / 10, seg = i - row * 10;
        uint32_t off = (uint32_t)(row * ATT_STRIDE + seg * 8) * 2;
        size_t g = hk + (size_t)row * 80 + seg * 8;
        CPA16(sb + OFF_KH + off, g_khi + g);
        CPA16(sb + OFF_KL + off, g_klo + g);
        CPA16(sb + OFF_VH + off, g_vhi + g);
        CPA16(sb + OFF_VL + off, g_vlo + g);
    }
    asm volatile("cp.async.commit_group;" ::: "memory");

    float m_a = -1e30f, m_b = -1e30f, l_a = 0.f, l_b = 0.f;
    float out[10][4];
#pragma unroll
    for (int vt = 0; vt < 10; vt++)
#pragma unroll
        for (int r = 0; r < 4; r++) out[vt][r] = 0.f;

    for (int t = 0; t < 16; t++) {
        if (t + 1 < 16) {
            const uint32_t s1 = ((t + 1) & 1) * T_BYTES;
            const size_t tb = hk + (size_t)(t + 1) * 64 * 80;
            for (int i = tid; i < 640; i += 256) {
                int row = i / 10, seg = i - row * 10;
                uint32_t off = (uint32_t)(row * ATT_STRIDE + seg * 8) * 2 + s1;
                size_t g = tb + (size_t)row * 80 + seg * 8;
                CPA16(sb + OFF_KH + off, g_khi + g);
                CPA16(sb + OFF_KL + off, g_klo + g);
                CPA16(sb + OFF_VH + off, g_vhi + g);
                CPA16(sb + OFF_VL + off, g_vlo + g);
            }
            asm volatile("cp.async.commit_group;" ::: "memory");
            asm volatile("cp.async.wait_group 1;" ::: "memory");
        } else {
            asm volatile("cp.async.wait_group 0;" ::: "memory");
        }
        __syncthreads();

        const uint32_t stg = (t & 1) * T_BYTES;
        const uint32_t KHs = sb + OFF_KH + stg;
        const uint32_t KLs = sb + OFF_KL + stg;
        const uint32_t VHs = sb + OFF_VH + stg;
        const uint32_t VLs = sb + OFF_VL + stg;

        float sc[8][4];
#pragma unroll
        for (int nt = 0; nt < 8; nt++)
#pragma unroll
            for (int r = 0; r < 4; r++) sc[nt][r] = 0.f;

        const int arow = w * 16 + (quad & 1) * 8 + l8;
#pragma unroll
        for (int kk = 0; kk < 5; kk++) {
            uint32_t ah[4], al[4];
            uint32_t aoff = (uint32_t)(arow * ATT_STRIDE + kk * 16 + (quad >> 1) * 8) * 2;
            LDSM4(ah, sb + OFF_QH + aoff);
            LDSM4(al, sb + OFF_QL + aoff);
#pragma unroll
            for (int nj = 0; nj < 4; nj++) {
                uint32_t bh[4], bl[4];
                uint32_t boff = (uint32_t)((nj * 16 + (quad >> 1) * 8 + l8) * ATT_STRIDE
                                           + kk * 16 + (quad & 1) * 8) * 2;
                LDSM4(bh, KHs + boff);
                LDSM4(bl, KLs + boff);
                MMA4(sc[2 * nj],     ah, bh[0], bh[1]);
                MMA4(sc[2 * nj],     ah, bl[0], bl[1]);
                MMA4(sc[2 * nj],     al, bh[0], bh[1]);
                MMA4(sc[2 * nj + 1], ah, bh[2], bh[3]);
                MMA4(sc[2 * nj + 1], ah, bl[2], bl[3]);
                MMA4(sc[2 * nj + 1], al, bh[2], bh[3]);
            }
        }

        float mxa = sc[0][0], mxb = sc[0][2];
#pragma unroll
        for (int nt = 0; nt < 8; nt++) {
            mxa = fmaxf(mxa, fmaxf(sc[nt][0], sc[nt][1]));
            mxb = fmaxf(mxb, fmaxf(sc[nt][2], sc[nt][3]));
        }
        mxa = fmaxf(mxa, __shfl_xor_sync(0xffffffffu, mxa, 1));
        mxa = fmaxf(mxa, __shfl_xor_sync(0xffffffffu, mxa, 2));
        mxb = fmaxf(mxb, __shfl_xor_sync(0xffffffffu, mxb, 1));
        mxb = fmaxf(mxb, __shfl_xor_sync(0xffffffffu, mxb, 2));
        float nma = fmaxf(m_a, mxa), nmb = fmaxf(m_b, mxb);
        float ca  = __expf(m_a - nma), cb = __expf(m_b - nmb);
        m_a = nma; m_b = nmb;

        float sa = 0.f, sbv = 0.f;
#pragma unroll
        for (int nt = 0; nt < 8; nt++) {
            sc[nt][0] = __expf(sc[nt][0] - m_a);
            sc[nt][1] = __expf(sc[nt][1] - m_a);
            sc[nt][2] = __expf(sc[nt][2] - m_b);
            sc[nt][3] = __expf(sc[nt][3] - m_b);
            sa  += sc[nt][0] + sc[nt][1];
            sbv += sc[nt][2] + sc[nt][3];
        }
        sa  += __shfl_xor_sync(0xffffffffu, sa, 1);
        sa  += __shfl_xor_sync(0xffffffffu, sa, 2);
        sbv += __shfl_xor_sync(0xffffffffu, sbv, 1);
        sbv += __shfl_xor_sync(0xffffffffu, sbv, 2);
        l_a = l_a * ca + sa;
        l_b = l_b * cb + sbv;

        uint32_t Ph[4][4], Pl[4][4];
#pragma unroll
        for (int kk = 0; kk < 4; kk++) {
#pragma unroll
            for (int half = 0; half < 2; half++) {
                int nt = 2 * kk + half;
                uint32_t h0 = pk2(sc[nt][0], sc[nt][1]);
                uint32_t h1 = pk2(sc[nt][2], sc[nt][3]);
                Ph[kk][2 * half + 0] = h0;
                Ph[kk][2 * half + 1] = h1;
                Pl[kk][2 * half + 0] = pk2(sc[nt][0] - lo_of(h0), sc[nt][1] - hi_of(h0));
                Pl[kk][2 * half + 1] = pk2(sc[nt][2] - lo_of(h1), sc[nt][3] - hi_of(h1));
            }
        }

#pragma unroll
        for (int vt = 0; vt < 10; vt++) {
            out[vt][0] *= ca; out[vt][1] *= ca;
            out[vt][2] *= cb; out[vt][3] *= cb;
        }

#pragma unroll
        for (int kk = 0; kk < 4; kk++) {
#pragma unroll
            for (int vj = 0; vj < 5; vj++) {
                uint32_t vhf[4], vlf[4];
                uint32_t voff = (uint32_t)((kk * 16 + (quad & 1) * 8 + l8) * ATT_STRIDE
                                           + vj * 16 + (quad >> 1) * 8) * 2;
                LDSM4T(vhf, VHs + voff);
                LDSM4T(vlf, VLs + voff);
                MMA4(out[2 * vj],     Ph[kk], vhf[0], vhf[1]);
                MMA4(out[2 * vj],     Ph[kk], vlf[0], vlf[1]);
                MMA4(out[2 * vj],     Pl[kk], vhf[0], vhf[1]);
                MMA4(out[2 * vj + 1], Ph[kk], vhf[2], vhf[3]);
                MMA4(out[2 * vj + 1], Ph[kk], vlf[2], vlf[3]);
                MMA4(out[2 * vj + 1], Pl[kk], vhf[2], vhf[3]);
            }
        }
        __syncthreads();
    }

    float ila = 1.f / l_a, ilb = 1.f / l_b;
    int ra = c * L_ + qt * 128 + w * 16 + (lane >> 2);
    int colb = h * D_ + (lane & 3) * 2;
#pragma unroll
    for (int vt = 0; vt < 10; vt++) {
        int col = colb + vt * 8;
        float v0 = out[vt][0] * ila, v1 = out[vt][1] * ila;
        uint32_t hp = pk2(v0, v1);
        uint32_t lp = pk2(v0 - lo_of(hp), v1 - hi_of(hp));
        *(uint32_t*)(g_ahi + (size_t)ra * HID_ + col) = hp;
        *(uint32_t*)(g_alo + (size_t)ra * HID_ + col) = lp;
        float v2 = out[vt][2] * ilb, v3 = out[vt][3] * ilb;
        hp = pk2(v2, v3);
        lp = pk2(v2 - lo_of(hp), v3 - hi_of(hp));
        *(uint32_t*)(g_ahi + (size_t)(ra + 8) * HID_ + col) = hp;
        *(uint32_t*)(g_alo + (size_t)(ra + 8) * HID_ + col) = lp;
    }
}

// ---------------------------------------------------------------------------
// Launch pipeline
// ---------------------------------------------------------------------------
extern "C" void kernel_launch(void* const* d_in, const int* in_sizes, int n_in,
                              void* d_out, int out_size)
{
    const float* x     = (const float*)d_in[0];
    const float* cosp  = (const float*)d_in[1];
    const float* sinp  = (const float*)d_in[2];
    const float* Wqkv  = (const float*)d_in[3];
    const float* bqkv  = (const float*)d_in[4];
    const float* Wproj = (const float*)d_in[5];
    const float* bproj = (const float*)d_in[6];
    float* out = (float*)d_out;

    float* qkv_p;
    __nv_bfloat16 *xhi, *xlo, *wqh, *wql, *wph, *wpl, *ahi, *alo;
    cudaGetSymbolAddress((void**)&qkv_p, g_qkv);
    cudaGetSymbolAddress((void**)&xhi, g_xhi);
    cudaGetSymbolAddress((void**)&xlo, g_xlo);
    cudaGetSymbolAddress((void**)&wqh, g_wqt_hi);
    cudaGetSymbolAddress((void**)&wql, g_wqt_lo);
    cudaGetSymbolAddress((void**)&wph, g_wpt_hi);
    cudaGetSymbolAddress((void**)&wpl, g_wpt_lo);
    cudaGetSymbolAddress((void**)&ahi, g_ahi);
    cudaGetSymbolAddress((void**)&alo, g_alo);

    static int attr_set = 0;
    if (!attr_set) {
        cudaFuncSetAttribute(attn_mma,
                             cudaFuncAttributeMaxDynamicSharedMemorySize,
                             ATTN_SMEM_BYTES);
        cudaFuncSetAttribute(mma_gemm_bias,
                             cudaFuncAttributeMaxDynamicSharedMemorySize,
                             GEMM_SMEM_BYTES);
        cudaFuncSetAttribute(mma_gemm_bias_sm,
                             cudaFuncAttributeMaxDynamicSharedMemorySize,
                             GEMM_SM_SMEM_BYTES);
        attr_set = 1;
    }

    split_rows<<<(S_ * HID_ + 255) / 256, 256>>>(x, xhi, xlo, S_ * HID_);
    split_t<<<dim3(THREE_HID / 32, HID_ / 32), dim3(32, 8)>>>(Wqkv, wqh, wql, HID_, THREE_HID);
    split_t<<<dim3(HID_ / 32, HID_ / 32), dim3(32, 8)>>>(Wproj, wph, wpl, HID_, HID_);

    // QKV GEMM: proven R6 config
    mma_gemm_bias<<<dim3(THREE_HID / 128, S_ / 128), 256, GEMM_SMEM_BYTES>>>(
        xhi, xlo, wqh, wql, bqkv, qkv_p, S_, THREE_HID, HID_);

    rope_split<<<(S_ * HID_ + 255) / 256, 256>>>(cosp, sinp);

    attn_mma<<<C_ * H_ * (L_ / 128), 256, ATTN_SMEM_BYTES>>>();

    // proj GEMM: experimental 3-CTA/SM small-tile config
    mma_gemm_bias_sm<<<dim3(HID_ / 128, S_ / 64), 128, GEMM_SM_SMEM_BYTES>>>(
        ahi, alo, wph, wpl, bproj, out, S_, HID_, HID_);
}

// round 9
// speedup vs baseline: 1.7536x; 1.0043x over previous
#include <cuda_runtime.h>
#include <cuda_bf16.h>
#include <cstdint>
#include <math.h>

#define S_        8192
#define HID_      1280
#define H_        16
#define D_        80
#define C_        8
#define L_        1024
#define THREE_HID 3840

// ---------------------------------------------------------------------------
// Scratch (allocation-free rule: __device__ globals)
// ---------------------------------------------------------------------------
__device__ float g_qkv[(size_t)S_ * THREE_HID];
__device__ __nv_bfloat16 g_xhi[(size_t)S_ * HID_];
__device__ __nv_bfloat16 g_xlo[(size_t)S_ * HID_];
__device__ __nv_bfloat16 g_wqt_hi[(size_t)THREE_HID * HID_];  // Wqkv^T [N][K]
__device__ __nv_bfloat16 g_wqt_lo[(size_t)THREE_HID * HID_];
__device__ __nv_bfloat16 g_wpt_hi[(size_t)HID_ * HID_];       // Wproj^T [N][K]
__device__ __nv_bfloat16 g_wpt_lo[(size_t)HID_ * HID_];
__device__ __nv_bfloat16 g_ahi[(size_t)S_ * HID_];            // attn out hi/lo
__device__ __nv_bfloat16 g_alo[(size_t)S_ * HID_];
__device__ __nv_bfloat16 g_qhi[(size_t)H_ * S_ * D_];
__device__ __nv_bfloat16 g_qlo[(size_t)H_ * S_ * D_];
__device__ __nv_bfloat16 g_khi[(size_t)H_ * S_ * D_];
__device__ __nv_bfloat16 g_klo[(size_t)H_ * S_ * D_];
__device__ __nv_bfloat16 g_vhi[(size_t)H_ * S_ * D_];
__device__ __nv_bfloat16 g_vlo[(size_t)H_ * S_ * D_];

__device__ __forceinline__ uint32_t smem_u32(const void* p) {
    uint32_t a;
    asm("{ .reg .u64 t; cvta.to.shared.u64 t, %1; cvt.u32.u64 %0, t; }"
        : "=r"(a) : "l"(p));
    return a;
}
__device__ __forceinline__ uint32_t pk2(float lo, float hi) {
    uint32_t r;
    asm("cvt.rn.bf16x2.f32 %0, %1, %2;" : "=r"(r) : "f"(hi), "f"(lo));
    return r;
}
__device__ __forceinline__ float lo_of(uint32_t p) { return __uint_as_float(p << 16); }
__device__ __forceinline__ float hi_of(uint32_t p) { return __uint_as_float(p & 0xffff0000u); }

#define MMA4(cc, aa, b0, b1)                                                    \
    asm volatile("mma.sync.aligned.m16n8k16.row.col.f32.bf16.bf16.f32 "         \
                 "{%0,%1,%2,%3},{%4,%5,%6,%7},{%8,%9},{%0,%1,%2,%3};"           \
                 : "+f"((cc)[0]), "+f"((cc)[1]), "+f"((cc)[2]), "+f"((cc)[3])   \
                 : "r"((aa)[0]), "r"((aa)[1]), "r"((aa)[2]), "r"((aa)[3]),      \
                   "r"(b0), "r"(b1))
#define LDSM4(r, addr)                                                          \
    asm volatile("ldmatrix.sync.aligned.m8n8.x4.shared.b16 {%0,%1,%2,%3}, [%4];"\
                 : "=r"((r)[0]), "=r"((r)[1]), "=r"((r)[2]), "=r"((r)[3])       \
                 : "r"(addr))
#define LDSM4T(r, addr)                                                         \
    asm volatile("ldmatrix.sync.aligned.m8n8.x4.trans.shared.b16 {%0,%1,%2,%3}, [%4];" \
                 : "=r"((r)[0]), "=r"((r)[1]), "=r"((r)[2]), "=r"((r)[3])       \
                 : "r"(addr))
#define CPA16(dst, src)                                                         \
    asm volatile("cp.async.cg.shared.global [%0], [%1], 16;" :: "r"(dst), "l"(src))

// ---------------------------------------------------------------------------
// bf16-split conversion kernels
// ---------------------------------------------------------------------------
__global__ void split_rows(const float* __restrict__ in,
                           __nv_bfloat16* __restrict__ hi,
                           __nv_bfloat16* __restrict__ lo, int n)
{
    int i = blockIdx.x * blockDim.x + threadIdx.x;
    if (i >= n) return;
    float v = in[i];
    __nv_bfloat16 h = __float2bfloat16(v);
    hi[i] = h;
    lo[i] = __float2bfloat16(v - __bfloat162float(h));
}

__global__ void split_t(const float* __restrict__ W,
                        __nv_bfloat16* __restrict__ hi,
                        __nv_bfloat16* __restrict__ lo, int K, int N)
{
    __shared__ float t[32][33];
    int n0 = blockIdx.x * 32, k0 = blockIdx.y * 32;
    int tx = threadIdx.x, ty = threadIdx.y;   // (32, 8)
#pragma unroll
    for (int i = 0; i < 32; i += 8)
        t[ty + i][tx] = W[(size_t)(k0 + ty + i) * N + n0 + tx];
    __syncthreads();
#pragma unroll
    for (int i = 0; i < 32; i += 8) {
        float v = t[tx][ty + i];
        __nv_bfloat16 h = __float2bfloat16(v);
        size_t o = (size_t)(n0 + ty + i) * K + k0 + tx;
        hi[o] = h;
        lo[o] = __float2bfloat16(v - __bfloat162float(h));
    }
}

// ---------------------------------------------------------------------------
// Small-CTA bf16-split GEMM (R8-proven best): C = A @ B^T + bias.
// 64(M) x 128(N) tile, BK=32, 128 threads (4 warps, warp tile 32x64),
// double-buffered cp.async, 3 CTAs/SM (three independent barrier domains).
// 3-term split: Ah*Bh + Ah*Bl + Al*Bh.
// ---------------------------------------------------------------------------
#define AST 40
#define A64_BYTES (64 * AST * 2)           // 5120
#define B128_BYTES (128 * AST * 2)         // 10240
#define STAGE_SM (2 * A64_BYTES + 2 * B128_BYTES)   // 30720
#define GEMM_SM_SMEM_BYTES (2 * STAGE_SM)           // 61440

__global__ __launch_bounds__(128, 3) void mma_gemm_bias_sm(
    const __nv_bfloat16* __restrict__ Ahi, const __nv_bfloat16* __restrict__ Alo,
    const __nv_bfloat16* __restrict__ Bhi, const __nv_bfloat16* __restrict__ Blo,
    const float* __restrict__ bias, float* __restrict__ Cm,
    int M, int N, int K)
{
    extern __shared__ __nv_bfloat16 smb[];
    const uint32_t sb = smem_u32(smb);

    const int tid  = threadIdx.x;
    const int lane = tid & 31, warp = tid >> 5;   // 0..3
    const int warpM = warp & 1;                   // rows warpM*32
    const int warpN = warp >> 1;                  // cols warpN*64
    const int quad = lane >> 3, l8 = lane & 7;
    const int tileN = blockIdx.x, tileM = blockIdx.y;

    const __nv_bfloat16* gAh = Ahi + (size_t)(tileM * 64) * K;
    const __nv_bfloat16* gAl = Alo + (size_t)(tileM * 64) * K;
    const __nv_bfloat16* gBh = Bhi + (size_t)(tileN * 128) * K;
    const __nv_bfloat16* gBl = Blo + (size_t)(tileN * 128) * K;

    float c[2][8][4];
#pragma unroll
    for (int mi = 0; mi < 2; mi++)
#pragma unroll
        for (int nt = 0; nt < 8; nt++)
#pragma unroll
            for (int r = 0; r < 4; r++) c[mi][nt][r] = 0.f;

    const int nch = K >> 5;

    auto issue = [&](int ch, int buf) {
        const int k0 = ch * 32;
        const uint32_t base = sb + (uint32_t)(buf * STAGE_SM);
#pragma unroll
        for (int p = 0; p < 2; p++) {    // A: 64 rows x 4 segs = 256 slots
            int idx = tid + p * 128;
            int row = idx >> 2, seg = idx & 3;
            uint32_t so = (uint32_t)((row * AST + seg * 8) * 2);
            size_t go = (size_t)row * K + k0 + seg * 8;
            CPA16(base + so,             gAh + go);
            CPA16(base + A64_BYTES + so, gAl + go);
        }
#pragma unroll
        for (int p = 0; p < 4; p++) {    // B: 128 rows x 4 segs = 512 slots
            int idx = tid + p * 128;
            int row = idx >> 2, seg = idx & 3;
            uint32_t so = (uint32_t)((row * AST + seg * 8) * 2);
            size_t go = (size_t)row * K + k0 + seg * 8;
            CPA16(base + 2 * A64_BYTES + so,              gBh + go);
            CPA16(base + 2 * A64_BYTES + B128_BYTES + so, gBl + go);
        }
        asm volatile("cp.async.commit_group;" ::: "memory");
    };

    issue(0, 0);

    for (int ch = 0; ch < nch; ch++) {
        if (ch + 1 < nch) {
            issue(ch + 1, (ch + 1) & 1);
            asm volatile("cp.async.wait_group 1;" ::: "memory");
        } else {
            asm volatile("cp.async.wait_group 0;" ::: "memory");
        }
        __syncthreads();

        const uint32_t base = sb + (uint32_t)((ch & 1) * STAGE_SM);
        const uint32_t aHb = base;
        const uint32_t aLb = base + A64_BYTES;
        const uint32_t bHb = base + 2 * A64_BYTES;
        const uint32_t bLb = base + 2 * A64_BYTES + B128_BYTES;

#pragma unroll
        for (int s = 0; s < 2; s++) {
            uint32_t ah[2][4], al[2][4], bh[4][4], bl[4][4];
#pragma unroll
            for (int mi = 0; mi < 2; mi++) {
                int row = warpM * 32 + mi * 16 + (quad & 1) * 8 + l8;
                int ke  = s * 16 + (quad >> 1) * 8;
                LDSM4(ah[mi], aHb + (uint32_t)((row * AST + ke) * 2));
                LDSM4(al[mi], aLb + (uint32_t)((row * AST + ke) * 2));
            }
#pragma unroll
            for (int nj = 0; nj < 4; nj++) {
                int nrow = warpN * 64 + nj * 16 + (quad >> 1) * 8 + l8;
                int ke   = s * 16 + (quad & 1) * 8;
                LDSM4(bh[nj], bHb + (uint32_t)((nrow * AST + ke) * 2));
                LDSM4(bl[nj], bLb + (uint32_t)((nrow * AST + ke) * 2));
            }
#pragma unroll
            for (int mi = 0; mi < 2; mi++) {
#pragma unroll
                for (int nt = 0; nt < 8; nt++) {
                    int nj = nt >> 1, hh = (nt & 1) * 2;
                    MMA4(c[mi][nt], ah[mi], bh[nj][hh], bh[nj][hh + 1]);
                    MMA4(c[mi][nt], ah[mi], bl[nj][hh], bl[nj][hh + 1]);
                    MMA4(c[mi][nt], al[mi], bh[nj][hh], bh[nj][hh + 1]);
                }
            }
        }
        __syncthreads();
    }

    const int m0 = tileM * 64 + warpM * 32;
    const int n0 = tileN * 128 + warpN * 64;
    const int rq = lane >> 2, cq = (lane & 3) * 2;
#pragma unroll
    for (int mi = 0; mi < 2; mi++) {
#pragma unroll
        for (int nt = 0; nt < 8; nt++) {
            int col = n0 + nt * 8 + cq;
            float2 b2 = *(const float2*)(bias + col);
            int r0 = m0 + mi * 16 + rq;
            float2 o0, o1;
            o0.x = c[mi][nt][0] + b2.x; o0.y = c[mi][nt][1] + b2.y;
            o1.x = c[mi][nt][2] + b2.x; o1.y = c[mi][nt][3] + b2.y;
            *(float2*)(Cm + (size_t)r0 * N + col)       = o0;
            *(float2*)(Cm + (size_t)(r0 + 8) * N + col) = o1;
        }
    }
}

// ---------------------------------------------------------------------------
// RoPE + split: qkv[S,3*HID] -> bf16 hi/lo Q (pre-scaled), K, V in [H][S][D]
// ---------------------------------------------------------------------------
__global__ void rope_split(const float* __restrict__ cosp,
                           const float* __restrict__ sinp)
{
    int idx = blockIdx.x * blockDim.x + threadIdx.x;
    if (idx >= S_ * HID_) return;
    int s   = idx / HID_;
    int col = idx - s * HID_;
    int h   = col / D_;
    int d   = col - h * D_;

    const float* base = g_qkv + (size_t)s * THREE_HID;
    float qv = base[col];
    float kv = base[HID_ + col];
    float vv = base[2 * HID_ + col];

    float cc = cosp[s * D_ + d];
    float sn = sinp[s * D_ + d];

    int off = (d < 40) ? (col + 40) : (col - 40);
    float sgn = (d < 40) ? -1.f : 1.f;
    float qrot = sgn * base[off];
    float krot = sgn * base[HID_ + off];

    const float inv_scale = rsqrtf((float)D_);
    float qf = (qv * cc + qrot * sn) * inv_scale;
    float kf = kv * cc + krot * sn;

    size_t o = (size_t)h * S_ * D_ + (size_t)s * D_ + d;
    __nv_bfloat16 qh = __float2bfloat16(qf);
    __nv_bfloat16 kh = __float2bfloat16(kf);
    __nv_bfloat16 vh = __float2bfloat16(vv);
    g_qhi[o] = qh; g_qlo[o] = __float2bfloat16(qf - __bfloat162float(qh));
    g_khi[o] = kh; g_klo[o] = __float2bfloat16(kf - __bfloat162float(kh));
    g_vhi[o] = vh; g_vlo[o] = __float2bfloat16(vv - __bfloat162float(vh));
}

// ---------------------------------------------------------------------------
// HMMA flash attention. 128q rows/CTA, 64k tiles, 8 warps (16 rows each).
// ---------------------------------------------------------------------------
#define ATT_STRIDE 88
#define Q_BYTES (128 * ATT_STRIDE * 2)
#define T_BYTES (64 * ATT_STRIDE * 2)
#define OFF_QH 0
#define OFF_QL Q_BYTES
#define OFF_KH (2 * Q_BYTES)
#define OFF_KL (2 * Q_BYTES + 2 * T_BYTES)
#define OFF_VH (2 * Q_BYTES + 4 * T_BYTES)
#define OFF_VL (2 * Q_BYTES + 6 * T_BYTES)
#define ATTN_SMEM_BYTES (2 * Q_BYTES + 8 * T_BYTES)   // 135168

__global__ __launch_bounds__(256) void attn_mma()
{
    extern __shared__ char smc[];
    const uint32_t sb = smem_u32(smc);

    const int bx = blockIdx.x;
    const int qt = bx & 7;
    const int h  = (bx >> 3) & 15;
    const int c  = bx >> 7;

    const int tid = threadIdx.x;
    const int lane = tid & 31, w = tid >> 5;
    const int quad = lane >> 3, l8 = lane & 7;

    const size_t hq = (size_t)h * S_ * D_ + (size_t)(c * L_ + qt * 128) * D_;
    const size_t hk = (size_t)h * S_ * D_ + (size_t)(c * L_) * D_;

    for (int i = tid; i < 1280; i += 256) {
        int row = i / 10, seg = i - row * 10;
        uint32_t off = (uint32_t)(row * ATT_STRIDE + seg * 8) * 2;
        size_t g = hq + (size_t)row * 80 + seg * 8;
        CPA16(sb + OFF_QH + off, g_qhi + g);
        CPA16(sb + OFF_QL + off, g_qlo + g);
    }
    for (int i = tid; i < 640; i += 256) {
        int row = i / 10, seg = i - row * 10;
        uint32_t off = (uint32_t)(row * ATT_STRIDE + seg * 8) * 2;
        size_t g = hk + (size_t)row * 80 + seg * 8;
        CPA16(sb + OFF_KH + off, g_khi + g);
        CPA16(sb + OFF_KL + off, g_klo + g);
        CPA16(sb + OFF_VH + off, g_vhi + g);
        CPA16(sb + OFF_VL + off, g_vlo + g);
    }
    asm volatile("cp.async.commit_group;" ::: "memory");

    float m_a = -1e30f, m_b = -1e30f, l_a = 0.f, l_b = 0.f;
    float out[10][4];
#pragma unroll
    for (int vt = 0; vt < 10; vt++)
#pragma unroll
        for (int r = 0; r < 4; r++) out[vt][r] = 0.f;

    for (int t = 0; t < 16; t++) {
        if (t + 1 < 16) {
            const uint32_t s1 = ((t + 1) & 1) * T_BYTES;
            const size_t tb = hk + (size_t)(t + 1) * 64 * 80;
            for (int i = tid; i < 640; i += 256) {
                int row = i / 10, seg = i - row * 10;
                uint32_t off = (uint32_t)(row * ATT_STRIDE + seg * 8) * 2 + s1;
                size_t g = tb + (size_t)row * 80 + seg * 8;
                CPA16(sb + OFF_KH + off, g_khi + g);
                CPA16(sb + OFF_KL + off, g_klo + g);
                CPA16(sb + OFF_VH + off, g_vhi + g);
                CPA16(sb + OFF_VL + off, g_vlo + g);
            }
            asm volatile("cp.async.commit_group;" ::: "memory");
            asm volatile("cp.async.wait_group 1;" ::: "memory");
        } else {
            asm volatile("cp.async.wait_group 0;" ::: "memory");
        }
        __syncthreads();

        const uint32_t stg = (t & 1) * T_BYTES;
        const uint32_t KHs = sb + OFF_KH + stg;
        const uint32_t KLs = sb + OFF_KL + stg;
        const uint32_t VHs = sb + OFF_VH + stg;
        const uint32_t VLs = sb + OFF_VL + stg;

        float sc[8][4];
#pragma unroll
        for (int nt = 0; nt < 8; nt++)
#pragma unroll
            for (int r = 0; r < 4; r++) sc[nt][r] = 0.f;

        const int arow = w * 16 + (quad & 1) * 8 + l8;
#pragma unroll
        for (int kk = 0; kk < 5; kk++) {
            uint32_t ah[4], al[4];
            uint32_t aoff = (uint32_t)(arow * ATT_STRIDE + kk * 16 + (quad >> 1) * 8) * 2;
            LDSM4(ah, sb + OFF_QH + aoff);
            LDSM4(al, sb + OFF_QL + aoff);
#pragma unroll
            for (int nj = 0; nj < 4; nj++) {
                uint32_t bh[4], bl[4];
                uint32_t boff = (uint32_t)((nj * 16 + (quad >> 1) * 8 + l8) * ATT_STRIDE
                                           + kk * 16 + (quad & 1) * 8) * 2;
                LDSM4(bh, KHs + boff);
                LDSM4(bl, KLs + boff);
                MMA4(sc[2 * nj],     ah, bh[0], bh[1]);
                MMA4(sc[2 * nj],     ah, bl[0], bl[1]);
                MMA4(sc[2 * nj],     al, bh[0], bh[1]);
                MMA4(sc[2 * nj + 1], ah, bh[2], bh[3]);
                MMA4(sc[2 * nj + 1], ah, bl[2], bl[3]);
                MMA4(sc[2 * nj + 1], al, bh[2], bh[3]);
            }
        }

        float mxa = sc[0][0], mxb = sc[0][2];
#pragma unroll
        for (int nt = 0; nt < 8; nt++) {
            mxa = fmaxf(mxa, fmaxf(sc[nt][0], sc[nt][1]));
            mxb = fmaxf(mxb, fmaxf(sc[nt][2], sc[nt][3]));
        }
        mxa = fmaxf(mxa, __shfl_xor_sync(0xffffffffu, mxa, 1));
        mxa = fmaxf(mxa, __shfl_xor_sync(0xffffffffu, mxa, 2));
        mxb = fmaxf(mxb, __shfl_xor_sync(0xffffffffu, mxb, 1));
        mxb = fmaxf(mxb, __shfl_xor_sync(0xffffffffu, mxb, 2));
        float nma = fmaxf(m_a, mxa), nmb = fmaxf(m_b, mxb);
        float ca  = __expf(m_a - nma), cb = __expf(m_b - nmb);
        m_a = nma; m_b = nmb;

        float sa = 0.f, sbv = 0.f;
#pragma unroll
        for (int nt = 0; nt < 8; nt++) {
            sc[nt][0] = __expf(sc[nt][0] - m_a);
            sc[nt][1] = __expf(sc[nt][1] - m_a);
            sc[nt][2] = __expf(sc[nt][2] - m_b);
            sc[nt][3] = __expf(sc[nt][3] - m_b);
            sa  += sc[nt][0] + sc[nt][1];
            sbv += sc[nt][2] + sc[nt][3];
        }
        sa  += __shfl_xor_sync(0xffffffffu, sa, 1);
        sa  += __shfl_xor_sync(0xffffffffu, sa, 2);
        sbv += __shfl_xor_sync(0xffffffffu, sbv, 1);
        sbv += __shfl_xor_sync(0xffffffffu, sbv, 2);
        l_a = l_a * ca + sa;
        l_b = l_b * cb + sbv;

        uint32_t Ph[4][4], Pl[4][4];
#pragma unroll
        for (int kk = 0; kk < 4; kk++) {
#pragma unroll
            for (int half = 0; half < 2; half++) {
                int nt = 2 * kk + half;
                uint32_t h0 = pk2(sc[nt][0], sc[nt][1]);
                uint32_t h1 = pk2(sc[nt][2], sc[nt][3]);
                Ph[kk][2 * half + 0] = h0;
                Ph[kk][2 * half + 1] = h1;
                Pl[kk][2 * half + 0] = pk2(sc[nt][0] - lo_of(h0), sc[nt][1] - hi_of(h0));
                Pl[kk][2 * half + 1] = pk2(sc[nt][2] - lo_of(h1), sc[nt][3] - hi_of(h1));
            }
        }

#pragma unroll
        for (int vt = 0; vt < 10; vt++) {
            out[vt][0] *= ca; out[vt][1] *= ca;
            out[vt][2] *= cb; out[vt][3] *= cb;
        }

#pragma unroll
        for (int kk = 0; kk < 4; kk++) {
#pragma unroll
            for (int vj = 0; vj < 5; vj++) {
                uint32_t vhf[4], vlf[4];
                uint32_t voff = (uint32_t)((kk * 16 + (quad & 1) * 8 + l8) * ATT_STRIDE
                                           + vj * 16 + (quad >> 1) * 8) * 2;
                LDSM4T(vhf, VHs + voff);
                LDSM4T(vlf, VLs + voff);
                MMA4(out[2 * vj],     Ph[kk], vhf[0], vhf[1]);
                MMA4(out[2 * vj],     Ph[kk], vlf[0], vlf[1]);
                MMA4(out[2 * vj],     Pl[kk], vhf[0], vhf[1]);
                MMA4(out[2 * vj + 1], Ph[kk], vhf[2], vhf[3]);
                MMA4(out[2 * vj + 1], Ph[kk], vlf[2], vlf[3]);
                MMA4(out[2 * vj + 1], Pl[kk], vhf[2], vhf[3]);
            }
        }
        __syncthreads();
    }

    float ila = 1.f / l_a, ilb = 1.f / l_b;
    int ra = c * L_ + qt * 128 + w * 16 + (lane >> 2);
    int colb = h * D_ + (lane & 3) * 2;
#pragma unroll
    for (int vt = 0; vt < 10; vt++) {
        int col = colb + vt * 8;
        float v0 = out[vt][0] * ila, v1 = out[vt][1] * ila;
        uint32_t hp = pk2(v0, v1);
        uint32_t lp = pk2(v0 - lo_of(hp), v1 - hi_of(hp));
        *(uint32_t*)(g_ahi + (size_t)ra * HID_ + col) = hp;
        *(uint32_t*)(g_alo + (size_t)ra * HID_ + col) = lp;
        float v2 = out[vt][2] * ilb, v3 = out[vt][3] * ilb;
        hp = pk2(v2, v3);
        lp = pk2(v2 - lo_of(hp), v3 - hi_of(hp));
        *(uint32_t*)(g_ahi + (size_t)(ra + 8) * HID_ + col) = hp;
        *(uint32_t*)(g_alo + (size_t)(ra + 8) * HID_ + col) = lp;
    }
}

// ---------------------------------------------------------------------------
// Launch pipeline
// ---------------------------------------------------------------------------
extern "C" void kernel_launch(void* const* d_in, const int* in_sizes, int n_in,
                              void* d_out, int out_size)
{
    const float* x     = (const float*)d_in[0];
    const float* cosp  = (const float*)d_in[1];
    const float* sinp  = (const float*)d_in[2];
    const float* Wqkv  = (const float*)d_in[3];
    const float* bqkv  = (const float*)d_in[4];
    const float* Wproj = (const float*)d_in[5];
    const float* bproj = (const float*)d_in[6];
    float* out = (float*)d_out;

    float* qkv_p;
    __nv_bfloat16 *xhi, *xlo, *wqh, *wql, *wph, *wpl, *ahi, *alo;
    cudaGetSymbolAddress((void**)&qkv_p, g_qkv);
    cudaGetSymbolAddress((void**)&xhi, g_xhi);
    cudaGetSymbolAddress((void**)&xlo, g_xlo);
    cudaGetSymbolAddress((void**)&wqh, g_wqt_hi);
    cudaGetSymbolAddress((void**)&wql, g_wqt_lo);
    cudaGetSymbolAddress((void**)&wph, g_wpt_hi);
    cudaGetSymbolAddress((void**)&wpl, g_wpt_lo);
    cudaGetSymbolAddress((void**)&ahi, g_ahi);
    cudaGetSymbolAddress((void**)&alo, g_alo);

    static int attr_set = 0;
    if (!attr_set) {
        cudaFuncSetAttribute(attn_mma,
                             cudaFuncAttributeMaxDynamicSharedMemorySize,
                             ATTN_SMEM_BYTES);
        cudaFuncSetAttribute(mma_gemm_bias_sm,
                             cudaFuncAttributeMaxDynamicSharedMemorySize,
                             GEMM_SM_SMEM_BYTES);
        attr_set = 1;
    }

    split_rows<<<(S_ * HID_ + 255) / 256, 256>>>(x, xhi, xlo, S_ * HID_);
    split_t<<<dim3(THREE_HID / 32, HID_ / 32), dim3(32, 8)>>>(Wqkv, wqh, wql, HID_, THREE_HID);
    split_t<<<dim3(HID_ / 32, HID_ / 32), dim3(32, 8)>>>(Wproj, wph, wpl, HID_, HID_);

    // QKV GEMM: 3-CTA/SM small-tile config (R8-proven on proj)
    mma_gemm_bias_sm<<<dim3(THREE_HID / 128, S_ / 64), 128, GEMM_SM_SMEM_BYTES>>>(
        xhi, xlo, wqh, wql, bqkv, qkv_p, S_, THREE_HID, HID_);

    rope_split<<<(S_ * HID_ + 255) / 256, 256>>>(cosp, sinp);

    attn_mma<<<C_ * H_ * (L_ / 128), 256, ATTN_SMEM_BYTES>>>();

    // proj GEMM: same config
    mma_gemm_bias_sm<<<dim3(HID_ / 128, S_ / 64), 128, GEMM_SM_SMEM_BYTES>>>(
        ahi, alo, wph, wpl, bproj, out, S_, HID_, HID_);
}

// round 10
// speedup vs baseline: 1.7825x; 1.0165x over previous
#include <cuda_runtime.h>
#include <cuda_bf16.h>
#include <cstdint>
#include <math.h>

#define S_        8192
#define HID_      1280
#define H_        16
#define D_        80
#define C_        8
#define L_        1024
#define THREE_HID 3840

// ---------------------------------------------------------------------------
// Scratch (allocation-free rule: __device__ globals)
// ---------------------------------------------------------------------------
__device__ float g_qkv[(size_t)S_ * THREE_HID];
__device__ __nv_bfloat16 g_xhi[(size_t)S_ * HID_];
__device__ __nv_bfloat16 g_xlo[(size_t)S_ * HID_];
__device__ __nv_bfloat16 g_wqt_hi[(size_t)THREE_HID * HID_];  // Wqkv^T [N][K]
__device__ __nv_bfloat16 g_wqt_lo[(size_t)THREE_HID * HID_];
__device__ __nv_bfloat16 g_wpt_hi[(size_t)HID_ * HID_];       // Wproj^T [N][K]
__device__ __nv_bfloat16 g_wpt_lo[(size_t)HID_ * HID_];
__device__ __nv_bfloat16 g_ahi[(size_t)S_ * HID_];            // attn out hi/lo
__device__ __nv_bfloat16 g_alo[(size_t)S_ * HID_];
__device__ __nv_bfloat16 g_qhi[(size_t)H_ * S_ * D_];
__device__ __nv_bfloat16 g_qlo[(size_t)H_ * S_ * D_];
__device__ __nv_bfloat16 g_khi[(size_t)H_ * S_ * D_];
__device__ __nv_bfloat16 g_klo[(size_t)H_ * S_ * D_];
__device__ __nv_bfloat16 g_vhi[(size_t)H_ * S_ * D_];
__device__ __nv_bfloat16 g_vlo[(size_t)H_ * S_ * D_];

__device__ __forceinline__ uint32_t smem_u32(const void* p) {
    uint32_t a;
    asm("{ .reg .u64 t; cvta.to.shared.u64 t, %1; cvt.u32.u64 %0, t; }"
        : "=r"(a) : "l"(p));
    return a;
}
__device__ __forceinline__ uint32_t pk2(float lo, float hi) {
    uint32_t r;
    asm("cvt.rn.bf16x2.f32 %0, %1, %2;" : "=r"(r) : "f"(hi), "f"(lo));
    return r;
}
__device__ __forceinline__ float lo_of(uint32_t p) { return __uint_as_float(p << 16); }
__device__ __forceinline__ float hi_of(uint32_t p) { return __uint_as_float(p & 0xffff0000u); }

#define MMA4(cc, aa, b0, b1)                                                    \
    asm volatile("mma.sync.aligned.m16n8k16.row.col.f32.bf16.bf16.f32 "         \
                 "{%0,%1,%2,%3},{%4,%5,%6,%7},{%8,%9},{%0,%1,%2,%3};"           \
                 : "+f"((cc)[0]), "+f"((cc)[1]), "+f"((cc)[2]), "+f"((cc)[3])   \
                 : "r"((aa)[0]), "r"((aa)[1]), "r"((aa)[2]), "r"((aa)[3]),      \
                   "r"(b0), "r"(b1))
#define LDSM4(r, addr)                                                          \
    asm volatile("ldmatrix.sync.aligned.m8n8.x4.shared.b16 {%0,%1,%2,%3}, [%4];"\
                 : "=r"((r)[0]), "=r"((r)[1]), "=r"((r)[2]), "=r"((r)[3])       \
                 : "r"(addr))
#define LDSM4T(r, addr)                                                         \
    asm volatile("ldmatrix.sync.aligned.m8n8.x4.trans.shared.b16 {%0,%1,%2,%3}, [%4];" \
                 : "=r"((r)[0]), "=r"((r)[1]), "=r"((r)[2]), "=r"((r)[3])       \
                 : "r"(addr))
#define CPA16(dst, src)                                                         \
    asm volatile("cp.async.cg.shared.global [%0], [%1], 16;" :: "r"(dst), "l"(src))

// ---------------------------------------------------------------------------
// bf16-split conversion kernels
// ---------------------------------------------------------------------------
__global__ void split_rows(const float* __restrict__ in,
                           __nv_bfloat16* __restrict__ hi,
                           __nv_bfloat16* __restrict__ lo, int n)
{
    int i = blockIdx.x * blockDim.x + threadIdx.x;
    if (i >= n) return;
    float v = in[i];
    __nv_bfloat16 h = __float2bfloat16(v);
    hi[i] = h;
    lo[i] = __float2bfloat16(v - __bfloat162float(h));
}

__global__ void split_t(const float* __restrict__ W,
                        __nv_bfloat16* __restrict__ hi,
                        __nv_bfloat16* __restrict__ lo, int K, int N)
{
    __shared__ float t[32][33];
    int n0 = blockIdx.x * 32, k0 = blockIdx.y * 32;
    int tx = threadIdx.x, ty = threadIdx.y;   // (32, 8)
#pragma unroll
    for (int i = 0; i < 32; i += 8)
        t[ty + i][tx] = W[(size_t)(k0 + ty + i) * N + n0 + tx];
    __syncthreads();
#pragma unroll
    for (int i = 0; i < 32; i += 8) {
        float v = t[tx][ty + i];
        __nv_bfloat16 h = __float2bfloat16(v);
        size_t o = (size_t)(n0 + ty + i) * K + k0 + tx;
        hi[o] = h;
        lo[o] = __float2bfloat16(v - __bfloat162float(h));
    }
}

// ---------------------------------------------------------------------------
// Small-CTA bf16-split GEMM (R8/R9 proven): C = A @ B^T + bias.
// 64(M) x 128(N) tile, BK=32, 128 threads (4 warps, warp tile 32x64),
// double-buffered cp.async, 3 CTAs/SM.  3-term split: Ah*Bh + Ah*Bl + Al*Bh.
// ---------------------------------------------------------------------------
#define AST 40
#define A64_BYTES (64 * AST * 2)           // 5120
#define B128_BYTES (128 * AST * 2)         // 10240
#define STAGE_SM (2 * A64_BYTES + 2 * B128_BYTES)   // 30720
#define GEMM_SM_SMEM_BYTES (2 * STAGE_SM)           // 61440

__global__ __launch_bounds__(128, 3) void mma_gemm_bias_sm(
    const __nv_bfloat16* __restrict__ Ahi, const __nv_bfloat16* __restrict__ Alo,
    const __nv_bfloat16* __restrict__ Bhi, const __nv_bfloat16* __restrict__ Blo,
    const float* __restrict__ bias, float* __restrict__ Cm,
    int M, int N, int K)
{
    extern __shared__ __nv_bfloat16 smb[];
    const uint32_t sb = smem_u32(smb);

    const int tid  = threadIdx.x;
    const int lane = tid & 31, warp = tid >> 5;   // 0..3
    const int warpM = warp & 1;
    const int warpN = warp >> 1;
    const int quad = lane >> 3, l8 = lane & 7;
    const int tileN = blockIdx.x, tileM = blockIdx.y;

    const __nv_bfloat16* gAh = Ahi + (size_t)(tileM * 64) * K;
    const __nv_bfloat16* gAl = Alo + (size_t)(tileM * 64) * K;
    const __nv_bfloat16* gBh = Bhi + (size_t)(tileN * 128) * K;
    const __nv_bfloat16* gBl = Blo + (size_t)(tileN * 128) * K;

    float c[2][8][4];
#pragma unroll
    for (int mi = 0; mi < 2; mi++)
#pragma unroll
        for (int nt = 0; nt < 8; nt++)
#pragma unroll
            for (int r = 0; r < 4; r++) c[mi][nt][r] = 0.f;

    const int nch = K >> 5;

    auto issue = [&](int ch, int buf) {
        const int k0 = ch * 32;
        const uint32_t base = sb + (uint32_t)(buf * STAGE_SM);
#pragma unroll
        for (int p = 0; p < 2; p++) {    // A: 64 rows x 4 segs
            int idx = tid + p * 128;
            int row = idx >> 2, seg = idx & 3;
            uint32_t so = (uint32_t)((row * AST + seg * 8) * 2);
            size_t go = (size_t)row * K + k0 + seg * 8;
            CPA16(base + so,             gAh + go);
            CPA16(base + A64_BYTES + so, gAl + go);
        }
#pragma unroll
        for (int p = 0; p < 4; p++) {    // B: 128 rows x 4 segs
            int idx = tid + p * 128;
            int row = idx >> 2, seg = idx & 3;
            uint32_t so = (uint32_t)((row * AST + seg * 8) * 2);
            size_t go = (size_t)row * K + k0 + seg * 8;
            CPA16(base + 2 * A64_BYTES + so,              gBh + go);
            CPA16(base + 2 * A64_BYTES + B128_BYTES + so, gBl + go);
        }
        asm volatile("cp.async.commit_group;" ::: "memory");
    };

    issue(0, 0);

    for (int ch = 0; ch < nch; ch++) {
        if (ch + 1 < nch) {
            issue(ch + 1, (ch + 1) & 1);
            asm volatile("cp.async.wait_group 1;" ::: "memory");
        } else {
            asm volatile("cp.async.wait_group 0;" ::: "memory");
        }
        __syncthreads();

        const uint32_t base = sb + (uint32_t)((ch & 1) * STAGE_SM);
        const uint32_t aHb = base;
        const uint32_t aLb = base + A64_BYTES;
        const uint32_t bHb = base + 2 * A64_BYTES;
        const uint32_t bLb = base + 2 * A64_BYTES + B128_BYTES;

#pragma unroll
        for (int s = 0; s < 2; s++) {
            uint32_t ah[2][4], al[2][4], bh[4][4], bl[4][4];
#pragma unroll
            for (int mi = 0; mi < 2; mi++) {
                int row = warpM * 32 + mi * 16 + (quad & 1) * 8 + l8;
                int ke  = s * 16 + (quad >> 1) * 8;
                LDSM4(ah[mi], aHb + (uint32_t)((row * AST + ke) * 2));
                LDSM4(al[mi], aLb + (uint32_t)((row * AST + ke) * 2));
            }
#pragma unroll
            for (int nj = 0; nj < 4; nj++) {
                int nrow = warpN * 64 + nj * 16 + (quad >> 1) * 8 + l8;
                int ke   = s * 16 + (quad & 1) * 8;
                LDSM4(bh[nj], bHb + (uint32_t)((nrow * AST + ke) * 2));
                LDSM4(bl[nj], bLb + (uint32_t)((nrow * AST + ke) * 2));
            }
#pragma unroll
            for (int mi = 0; mi < 2; mi++) {
#pragma unroll
                for (int nt = 0; nt < 8; nt++) {
                    int nj = nt >> 1, hh = (nt & 1) * 2;
                    MMA4(c[mi][nt], ah[mi], bh[nj][hh], bh[nj][hh + 1]);
                    MMA4(c[mi][nt], ah[mi], bl[nj][hh], bl[nj][hh + 1]);
                    MMA4(c[mi][nt], al[mi], bh[nj][hh], bh[nj][hh + 1]);
                }
            }
        }
        __syncthreads();
    }

    const int m0 = tileM * 64 + warpM * 32;
    const int n0 = tileN * 128 + warpN * 64;
    const int rq = lane >> 2, cq = (lane & 3) * 2;
#pragma unroll
    for (int mi = 0; mi < 2; mi++) {
#pragma unroll
        for (int nt = 0; nt < 8; nt++) {
            int col = n0 + nt * 8 + cq;
            float2 b2 = *(const float2*)(bias + col);
            int r0 = m0 + mi * 16 + rq;
            float2 o0, o1;
            o0.x = c[mi][nt][0] + b2.x; o0.y = c[mi][nt][1] + b2.y;
            o1.x = c[mi][nt][2] + b2.x; o1.y = c[mi][nt][3] + b2.y;
            *(float2*)(Cm + (size_t)r0 * N + col)       = o0;
            *(float2*)(Cm + (size_t)(r0 + 8) * N + col) = o1;
        }
    }
}

// ---------------------------------------------------------------------------
// RoPE + split: qkv[S,3*HID] -> bf16 hi/lo Q (pre-scaled), K, V in [H][S][D]
// ---------------------------------------------------------------------------
__global__ void rope_split(const float* __restrict__ cosp,
                           const float* __restrict__ sinp)
{
    int idx = blockIdx.x * blockDim.x + threadIdx.x;
    if (idx >= S_ * HID_) return;
    int s   = idx / HID_;
    int col = idx - s * HID_;
    int h   = col / D_;
    int d   = col - h * D_;

    const float* base = g_qkv + (size_t)s * THREE_HID;
    float qv = base[col];
    float kv = base[HID_ + col];
    float vv = base[2 * HID_ + col];

    float cc = cosp[s * D_ + d];
    float sn = sinp[s * D_ + d];

    int off = (d < 40) ? (col + 40) : (col - 40);
    float sgn = (d < 40) ? -1.f : 1.f;
    float qrot = sgn * base[off];
    float krot = sgn * base[HID_ + off];

    const float inv_scale = rsqrtf((float)D_);
    float qf = (qv * cc + qrot * sn) * inv_scale;
    float kf = kv * cc + krot * sn;

    size_t o = (size_t)h * S_ * D_ + (size_t)s * D_ + d;
    __nv_bfloat16 qh = __float2bfloat16(qf);
    __nv_bfloat16 kh = __float2bfloat16(kf);
    __nv_bfloat16 vh = __float2bfloat16(vv);
    g_qhi[o] = qh; g_qlo[o] = __float2bfloat16(qf - __bfloat162float(qh));
    g_khi[o] = kh; g_klo[o] = __float2bfloat16(kf - __bfloat162float(kh));
    g_vhi[o] = vh; g_vlo[o] = __float2bfloat16(vv - __bfloat162float(vh));
}

// ---------------------------------------------------------------------------
// HMMA flash attention. 64 q-rows/CTA, 64k tiles, 4 warps (16 rows each),
// 128 threads, 2 CTAs/SM (two independent barrier domains so one CTA's
// softmax phase overlaps the other CTA's MMA phase).
// ---------------------------------------------------------------------------
#define ATT_STRIDE 88
#define Q_BYTES (64 * ATT_STRIDE * 2)     // 11264
#define T_BYTES (64 * ATT_STRIDE * 2)     // 11264
#define OFF_QH 0
#define OFF_QL Q_BYTES
#define OFF_KH (2 * Q_BYTES)
#define OFF_KL (2 * Q_BYTES + 2 * T_BYTES)
#define OFF_VH (2 * Q_BYTES + 4 * T_BYTES)
#define OFF_VL (2 * Q_BYTES + 6 * T_BYTES)
#define ATTN_SMEM_BYTES (2 * Q_BYTES + 8 * T_BYTES)   // 112640

__global__ __launch_bounds__(128, 2) void attn_mma()
{
    extern __shared__ char smc[];
    const uint32_t sb = smem_u32(smc);

    const int bx = blockIdx.x;
    const int qt = bx & 15;           // 16 q-tiles of 64 rows
    const int h  = (bx >> 4) & 15;
    const int c  = bx >> 8;

    const int tid = threadIdx.x;
    const int lane = tid & 31, w = tid >> 5;   // w: 0..3
    const int quad = lane >> 3, l8 = lane & 7;

    const size_t hq = (size_t)h * S_ * D_ + (size_t)(c * L_ + qt * 64) * D_;
    const size_t hk = (size_t)h * S_ * D_ + (size_t)(c * L_) * D_;

    // issue Q (64x80) + KV tile 0 (one group)
    for (int i = tid; i < 640; i += 128) {
        int row = i / 10, seg = i - row * 10;
        uint32_t off = (uint32_t)(row * ATT_STRIDE + seg * 8) * 2;
        size_t g = hq + (size_t)row * 80 + seg * 8;
        CPA16(sb + OFF_QH + off, g_qhi + g);
        CPA16(sb + OFF_QL + off, g_qlo + g);
    }
    for (int i = tid; i < 640; i += 128) {
        int row = i / 10, seg = i - row * 10;
        uint32_t off = (uint32_t)(row * ATT_STRIDE + seg * 8) * 2;
        size_t g = hk + (size_t)row * 80 + seg * 8;
        CPA16(sb + OFF_KH + off, g_khi + g);
        CPA16(sb + OFF_KL + off, g_klo + g);
        CPA16(sb + OFF_VH + off, g_vhi + g);
        CPA16(sb + OFF_VL + off, g_vlo + g);
    }
    asm volatile("cp.async.commit_group;" ::: "memory");

    float m_a = -1e30f, m_b = -1e30f, l_a = 0.f, l_b = 0.f;
    float out[10][4];
#pragma unroll
    for (int vt = 0; vt < 10; vt++)
#pragma unroll
        for (int r = 0; r < 4; r++) out[vt][r] = 0.f;

    for (int t = 0; t < 16; t++) {
        if (t + 1 < 16) {
            const uint32_t s1 = ((t + 1) & 1) * T_BYTES;
            const size_t tb = hk + (size_t)(t + 1) * 64 * 80;
            for (int i = tid; i < 640; i += 128) {
                int row = i / 10, seg = i - row * 10;
                uint32_t off = (uint32_t)(row * ATT_STRIDE + seg * 8) * 2 + s1;
                size_t g = tb + (size_t)row * 80 + seg * 8;
                CPA16(sb + OFF_KH + off, g_khi + g);
                CPA16(sb + OFF_KL + off, g_klo + g);
                CPA16(sb + OFF_VH + off, g_vhi + g);
                CPA16(sb + OFF_VL + off, g_vlo + g);
            }
            asm volatile("cp.async.commit_group;" ::: "memory");
            asm volatile("cp.async.wait_group 1;" ::: "memory");
        } else {
            asm volatile("cp.async.wait_group 0;" ::: "memory");
        }
        __syncthreads();

        const uint32_t stg = (t & 1) * T_BYTES;
        const uint32_t KHs = sb + OFF_KH + stg;
        const uint32_t KLs = sb + OFF_KL + stg;
        const uint32_t VHs = sb + OFF_VH + stg;
        const uint32_t VLs = sb + OFF_VL + stg;

        float sc[8][4];
#pragma unroll
        for (int nt = 0; nt < 8; nt++)
#pragma unroll
            for (int r = 0; r < 4; r++) sc[nt][r] = 0.f;

        const int arow = w * 16 + (quad & 1) * 8 + l8;
#pragma unroll
        for (int kk = 0; kk < 5; kk++) {
            uint32_t ah[4], al[4];
            uint32_t aoff = (uint32_t)(arow * ATT_STRIDE + kk * 16 + (quad >> 1) * 8) * 2;
            LDSM4(ah, sb + OFF_QH + aoff);
            LDSM4(al, sb + OFF_QL + aoff);
#pragma unroll
            for (int nj = 0; nj < 4; nj++) {
                uint32_t bh[4], bl[4];
                uint32_t boff = (uint32_t)((nj * 16 + (quad >> 1) * 8 + l8) * ATT_STRIDE
                                           + kk * 16 + (quad & 1) * 8) * 2;
                LDSM4(bh, KHs + boff);
                LDSM4(bl, KLs + boff);
                MMA4(sc[2 * nj],     ah, bh[0], bh[1]);
                MMA4(sc[2 * nj],     ah, bl[0], bl[1]);
                MMA4(sc[2 * nj],     al, bh[0], bh[1]);
                MMA4(sc[2 * nj + 1], ah, bh[2], bh[3]);
                MMA4(sc[2 * nj + 1], ah, bl[2], bl[3]);
                MMA4(sc[2 * nj + 1], al, bh[2], bh[3]);
            }
        }

        float mxa = sc[0][0], mxb = sc[0][2];
#pragma unroll
        for (int nt = 0; nt < 8; nt++) {
            mxa = fmaxf(mxa, fmaxf(sc[nt][0], sc[nt][1]));
            mxb = fmaxf(mxb, fmaxf(sc[nt][2], sc[nt][3]));
        }
        mxa = fmaxf(mxa, __shfl_xor_sync(0xffffffffu, mxa, 1));
        mxa = fmaxf(mxa, __shfl_xor_sync(0xffffffffu, mxa, 2));
        mxb = fmaxf(mxb, __shfl_xor_sync(0xffffffffu, mxb, 1));
        mxb = fmaxf(mxb, __shfl_xor_sync(0xffffffffu, mxb, 2));
        float nma = fmaxf(m_a, mxa), nmb = fmaxf(m_b, mxb);
        float ca  = __expf(m_a - nma), cb = __expf(m_b - nmb);
        m_a = nma; m_b = nmb;

        float sa = 0.f, sbv = 0.f;
#pragma unroll
        for (int nt = 0; nt < 8; nt++) {
            sc[nt][0] = __expf(sc[nt][0] - m_a);
            sc[nt][1] = __expf(sc[nt][1] - m_a);
            sc[nt][2] = __expf(sc[nt][2] - m_b);
            sc[nt][3] = __expf(sc[nt][3] - m_b);
            sa  += sc[nt][0] + sc[nt][1];
            sbv += sc[nt][2] + sc[nt][3];
        }
        sa  += __shfl_xor_sync(0xffffffffu, sa, 1);
        sa  += __shfl_xor_sync(0xffffffffu, sa, 2);
        sbv += __shfl_xor_sync(0xffffffffu, sbv, 1);
        sbv += __shfl_xor_sync(0xffffffffu, sbv, 2);
        l_a = l_a * ca + sa;
        l_b = l_b * cb + sbv;

        uint32_t Ph[4][4], Pl[4][4];
#pragma unroll
        for (int kk = 0; kk < 4; kk++) {
#pragma unroll
            for (int half = 0; half < 2; half++) {
                int nt = 2 * kk + half;
                uint32_t h0 = pk2(sc[nt][0], sc[nt][1]);
                uint32_t h1 = pk2(sc[nt][2], sc[nt][3]);
                Ph[kk][2 * half + 0] = h0;
                Ph[kk][2 * half + 1] = h1;
                Pl[kk][2 * half + 0] = pk2(sc[nt][0] - lo_of(h0), sc[nt][1] - hi_of(h0));
                Pl[kk][2 * half + 1] = pk2(sc[nt][2] - lo_of(h1), sc[nt][3] - hi_of(h1));
            }
        }

#pragma unroll
        for (int vt = 0; vt < 10; vt++) {
            out[vt][0] *= ca; out[vt][1] *= ca;
            out[vt][2] *= cb; out[vt][3] *= cb;
        }

#pragma unroll
        for (int kk = 0; kk < 4; kk++) {
#pragma unroll
            for (int vj = 0; vj < 5; vj++) {
                uint32_t vhf[4], vlf[4];
                uint32_t voff = (uint32_t)((kk * 16 + (quad & 1) * 8 + l8) * ATT_STRIDE
                                           + vj * 16 + (quad >> 1) * 8) * 2;
                LDSM4T(vhf, VHs + voff);
                LDSM4T(vlf, VLs + voff);
                MMA4(out[2 * vj],     Ph[kk], vhf[0], vhf[1]);
                MMA4(out[2 * vj],     Ph[kk], vlf[0], vlf[1]);
                MMA4(out[2 * vj],     Pl[kk], vhf[0], vhf[1]);
                MMA4(out[2 * vj + 1], Ph[kk], vhf[2], vhf[3]);
                MMA4(out[2 * vj + 1], Ph[kk], vlf[2], vlf[3]);
                MMA4(out[2 * vj + 1], Pl[kk], vhf[2], vhf[3]);
            }
        }
        __syncthreads();
    }

    float ila = 1.f / l_a, ilb = 1.f / l_b;
    int ra = c * L_ + qt * 64 + w * 16 + (lane >> 2);
    int colb = h * D_ + (lane & 3) * 2;
#pragma unroll
    for (int vt = 0; vt < 10; vt++) {
        int col = colb + vt * 8;
        float v0 = out[vt][0] * ila, v1 = out[vt][1] * ila;
        uint32_t hp = pk2(v0, v1);
        uint32_t lp = pk2(v0 - lo_of(hp), v1 - hi_of(hp));
        *(uint32_t*)(g_ahi + (size_t)ra * HID_ + col) = hp;
        *(uint32_t*)(g_alo + (size_t)ra * HID_ + col) = lp;
        float v2 = out[vt][2] * ilb, v3 = out[vt][3] * ilb;
        hp = pk2(v2, v3);
        lp = pk2(v2 - lo_of(hp), v3 - hi_of(hp));
        *(uint32_t*)(g_ahi + (size_t)(ra + 8) * HID_ + col) = hp;
        *(uint32_t*)(g_alo + (size_t)(ra + 8) * HID_ + col) = lp;
    }
}

// ---------------------------------------------------------------------------
// Launch pipeline
// ---------------------------------------------------------------------------
extern "C" void kernel_launch(void* const* d_in, const int* in_sizes, int n_in,
                              void* d_out, int out_size)
{
    const float* x     = (const float*)d_in[0];
    const float* cosp  = (const float*)d_in[1];
    const float* sinp  = (const float*)d_in[2];
    const float* Wqkv  = (const float*)d_in[3];
    const float* bqkv  = (const float*)d_in[4];
    const float* Wproj = (const float*)d_in[5];
    const float* bproj = (const float*)d_in[6];
    float* out = (float*)d_out;

    float* qkv_p;
    __nv_bfloat16 *xhi, *xlo, *wqh, *wql, *wph, *wpl, *ahi, *alo;
    cudaGetSymbolAddress((void**)&qkv_p, g_qkv);
    cudaGetSymbolAddress((void**)&xhi, g_xhi);
    cudaGetSymbolAddress((void**)&xlo, g_xlo);
    cudaGetSymbolAddress((void**)&wqh, g_wqt_hi);
    cudaGetSymbolAddress((void**)&wql, g_wqt_lo);
    cudaGetSymbolAddress((void**)&wph, g_wpt_hi);
    cudaGetSymbolAddress((void**)&wpl, g_wpt_lo);
    cudaGetSymbolAddress((void**)&ahi, g_ahi);
    cudaGetSymbolAddress((void**)&alo, g_alo);

    static int attr_set = 0;
    if (!attr_set) {
        cudaFuncSetAttribute(attn_mma,
                             cudaFuncAttributeMaxDynamicSharedMemorySize,
                             ATTN_SMEM_BYTES);
        cudaFuncSetAttribute(mma_gemm_bias_sm,
                             cudaFuncAttributeMaxDynamicSharedMemorySize,
                             GEMM_SM_SMEM_BYTES);
        attr_set = 1;
    }

    split_rows<<<(S_ * HID_ + 255) / 256, 256>>>(x, xhi, xlo, S_ * HID_);
    split_t<<<dim3(THREE_HID / 32, HID_ / 32), dim3(32, 8)>>>(Wqkv, wqh, wql, HID_, THREE_HID);
    split_t<<<dim3(HID_ / 32, HID_ / 32), dim3(32, 8)>>>(Wproj, wph, wpl, HID_, HID_);

    mma_gemm_bias_sm<<<dim3(THREE_HID / 128, S_ / 64), 128, GEMM_SM_SMEM_BYTES>>>(
        xhi, xlo, wqh, wql, bqkv, qkv_p, S_, THREE_HID, HID_);

    rope_split<<<(S_ * HID_ + 255) / 256, 256>>>(cosp, sinp);

    attn_mma<<<C_ * H_ * (L_ / 64), 128, ATTN_SMEM_BYTES>>>();

    mma_gemm_bias_sm<<<dim3(HID_ / 128, S_ / 64), 128, GEMM_SM_SMEM_BYTES>>>(
        ahi, alo, wph, wpl, bproj, out, S_, HID_, HID_);
}